// round 11
// baseline (speedup 1.0000x reference)
#include <cuda_runtime.h>
#include <cuda_fp16.h>
#include <cstdint>

#define Bv 8
#define Nv 1024
#define Dv 768
#define Hv 12
#define HDv 64
#define Mv (Bv*Nv)      /* 8192 */
#define E3v (3*Dv)      /* 2304 */

// folded into Q at QKV epilogue: 1/sqrt(64) * log2(e)
#define QSC 0.18033688011112042f

// Scratch (device globals, fp16)
__device__ __half g_q[Bv*Hv*Nv*HDv];   // [B*H][N][64], pre-scaled by QSC
__device__ __half g_k[Bv*Hv*Nv*HDv];   // [B*H][N][64]
__device__ __half g_v[Bv*Hv*Nv*HDv];   // [B*H][64][N]  (d-major)
__device__ __half g_o[Mv*Dv];          // [B][N][D]
__device__ __half g_xc[Mv*Dv];
__device__ __half g_wq[E3v*Dv];
__device__ __half g_wp[Dv*Dv];

// ============================================================================
// Helpers
// ============================================================================
__device__ __forceinline__ uint32_t smem_u32(const void* p) {
    uint32_t a;
    asm("{ .reg .u64 t; cvta.to.shared.u64 t, %1; cvt.u32.u64 %0, t; }"
        : "=r"(a) : "l"(p));
    return a;
}
__device__ __forceinline__ void cp16(uint32_t dst, const void* src) {
    asm volatile("cp.async.cg.shared.global [%0], [%1], 16;" :: "r"(dst), "l"(src));
}
__device__ __forceinline__ void ldm_x4(uint32_t r[4], uint32_t addr) {
    asm volatile("ldmatrix.sync.aligned.m8n8.x4.shared.b16 {%0,%1,%2,%3}, [%4];"
        : "=r"(r[0]), "=r"(r[1]), "=r"(r[2]), "=r"(r[3]) : "r"(addr));
}
__device__ __forceinline__ void mma_f16(float c[4], const uint32_t a[4],
                                        uint32_t b0, uint32_t b1) {
    asm volatile(
        "mma.sync.aligned.m16n8k16.row.col.f32.f16.f16.f32 "
        "{%0,%1,%2,%3}, {%4,%5,%6,%7}, {%8,%9}, {%0,%1,%2,%3};"
        : "+f"(c[0]), "+f"(c[1]), "+f"(c[2]), "+f"(c[3])
        : "r"(a[0]), "r"(a[1]), "r"(a[2]), "r"(a[3]), "r"(b0), "r"(b1));
}
// MUFU exp2 (2-ulp approx; underflows to 0 for large-negative inputs)
__device__ __forceinline__ float ex2(float d) {
    float r;
    asm("ex2.approx.f32 %0, %1;" : "=f"(r) : "f"(d));
    return r;
}
__device__ __forceinline__ uint32_t h2u(__half2 h) {
    return *reinterpret_cast<uint32_t*>(&h);
}

// ============================================================================
// Merged fp16 conversion prepass (x, Wqkv, Wproj)
// ============================================================================
#define N4X (Mv*Dv/4)
#define N4Q (E3v*Dv/4)
#define N4P (Dv*Dv/4)
#define N4ALL (N4X + N4Q + N4P)

__global__ void cvt_all_k(const float4* __restrict__ x,
                          const float4* __restrict__ wq,
                          const float4* __restrict__ wp)
{
    int i = blockIdx.x * 256 + threadIdx.x;
    if (i >= N4ALL) return;
    float4 v;
    uint2* d;
    if (i < N4X)            { v = x[i];                d = (uint2*)g_xc + i; }
    else if (i < N4X + N4Q) { v = wq[i - N4X];         d = (uint2*)g_wq + (i - N4X); }
    else                    { v = wp[i - N4X - N4Q];   d = (uint2*)g_wp + (i - N4X - N4Q); }
    *d = make_uint2(h2u(__floats2half2_rn(v.x, v.y)),
                    h2u(__floats2half2_rn(v.z, v.w)));
}

// ============================================================================
// fp16 mma.sync GEMM (NT): 128x128 tile, 128 threads / 4 warps (2x2),
// warp tile 64x64 (big-ILP), K-chunk 64, 3-stage ring, 2 CTAs/SM.
// MODE 0: A=g_xc, B=g_wq -> scatter into g_q (xQSC) / g_k / g_v(transposed)
// MODE 1: A=g_o,  B=g_wp -> out + bias (fp32)
// ============================================================================
#define KCH 64
#define NCH (Dv / KCH)               /* 12 */
#define LDPH 72                      /* pitch in halves (144B rows) */
#define STG_H (128 * LDPH)
#define GSMEM (3 * 2 * STG_H * 2)    /* 110592 bytes */

template<int MODE>
__global__ __launch_bounds__(128, 2) void gemm_mma(
    const __half* __restrict__ A, const __half* __restrict__ Bw,
    const float* __restrict__ bias, float* __restrict__ out)
{
    extern __shared__ __align__(16) __half shh[];
    const int tid = threadIdx.x;          // 0..127
    const int w = tid >> 5, lane = tid & 31;
    const int lq = lane >> 2, lr4 = lane & 3;
    const int lrow = ((lane >> 3) & 1) * 8 + (lane & 7);
    const int lcol = (lane >> 4) * 8;
    const int wm = (w & 1) * 64, wn = (w >> 1) * 64;
    const int m0 = blockIdx.y * 128, e0 = blockIdx.x * 128;

    float c[4][8][4];                     // 128 accumulators
    #pragma unroll
    for (int i = 0; i < 4; i++)
        #pragma unroll
        for (int j = 0; j < 8; j++)
            #pragma unroll
            for (int r = 0; r < 4; r++) c[i][j][r] = 0.f;

    auto load_st = [&](int ch, int stg) {
        __half* Ab = shh + stg * 2 * STG_H;
        __half* Bb = Ab + STG_H;
        const __half* Ag = A + (size_t)m0 * Dv + ch * KCH;
        const __half* Bg = Bw + (size_t)e0 * Dv + ch * KCH;
        #pragma unroll
        for (int u = 0; u < 8; u++) {
            int idx = tid + 128 * u;      // 0..1023 = 128 rows x 8 segs
            int row = idx >> 3, q = idx & 7;
            cp16(smem_u32(Ab + row * LDPH + q * 8), Ag + (size_t)row * Dv + q * 8);
            cp16(smem_u32(Bb + row * LDPH + q * 8), Bg + (size_t)row * Dv + q * 8);
        }
        asm volatile("cp.async.commit_group;" ::: "memory");
    };

    load_st(0, 0);
    load_st(1, 1);

    for (int ch = 0; ch < NCH; ch++) {
        if (ch < NCH - 1)
            asm volatile("cp.async.wait_group 1;" ::: "memory");
        else
            asm volatile("cp.async.wait_group 0;" ::: "memory");
        __syncthreads();
        if (ch + 2 < NCH) load_st(ch + 2, (ch + 2) % 3);

        const uint32_t ab32 = smem_u32(shh + (ch % 3) * 2 * STG_H);
        const uint32_t bb32 = ab32 + STG_H * 2;

        #pragma unroll
        for (int kk = 0; kk < 4; kk++) {
            uint32_t af[4][4];
            #pragma unroll
            for (int mf = 0; mf < 4; mf++)
                ldm_x4(af[mf], ab32 + ((wm + mf * 16 + lrow) * LDPH + kk * 16 + lcol) * 2);
            uint32_t bq[4][4];
            #pragma unroll
            for (int jn = 0; jn < 4; jn++)
                ldm_x4(bq[jn], bb32 + ((wn + jn * 16 + lrow) * LDPH + kk * 16 + lcol) * 2);
            #pragma unroll
            for (int mf = 0; mf < 4; mf++)
                #pragma unroll
                for (int jn = 0; jn < 4; jn++) {
                    mma_f16(c[mf][2 * jn],     af[mf], bq[jn][0], bq[jn][2]);
                    mma_f16(c[mf][2 * jn + 1], af[mf], bq[jn][1], bq[jn][3]);
                }
        }
    }

    // Epilogue
    #pragma unroll
    for (int nf = 0; nf < 8; nf++) {
        const int e = e0 + wn + nf * 8 + lr4 * 2;
        #pragma unroll
        for (int mf = 0; mf < 4; mf++) {
            #pragma unroll
            for (int half = 0; half < 2; half++) {
                const int m = m0 + wm + mf * 16 + lq + half * 8;
                float2 v = make_float2(c[mf][nf][half * 2], c[mf][nf][half * 2 + 1]);
                if (MODE == 0) {
                    const int b = m >> 10, n = m & 1023;
                    const int s = e / Dv, r = e - s * Dv;
                    const int hh = r >> 6, i2 = r & 63;
                    if (s == 0) { v.x *= QSC; v.y *= QSC; }
                    if (s < 2) {
                        __half* dst = ((s == 0) ? g_q : g_k)
                                    + (((size_t)(b * Hv + hh)) * Nv + n) * HDv + i2;
                        *(uint32_t*)dst = h2u(__floats2half2_rn(v.x, v.y));
                    } else {
                        __half* dst = g_v + ((size_t)(b * Hv + hh)) * HDv * Nv
                                    + (size_t)i2 * Nv + n;
                        dst[0]  = __float2half_rn(v.x);
                        dst[Nv] = __float2half_rn(v.y);
                    }
                } else {
                    v.x += bias[e];
                    v.y += bias[e + 1];
                    *(float2*)(out + (size_t)m * Dv + e) = v;
                }
            }
        }
    }
}

// ============================================================================
// fp16 mma.sync flash attention: 128 threads / 4 warps, warp tile m32,
// no-max softmax via MUFU ex2, P in registers, row sums via tensor core,
// 3-stage KV ring. CTA = (bh, 128-row q tile).
// ============================================================================
#define ATP 72
#define AT_SMEM ((3*64*ATP*2 + 128*ATP) * 2 + Nv * 4)   /* 77824 */
#define ONES_H2 0x3C003C00u   /* __half2(1,1) */

__global__ __launch_bounds__(128, 2) void attn_mma(const int* __restrict__ maskg)
{
    extern __shared__ __align__(16) __half sha[];

    const int tid = threadIdx.x;          // 0..127
    const int w = tid >> 5, lane = tid & 31;
    const int lq = lane >> 2, lr4 = lane & 3;
    const int lrow = ((lane >> 3) & 1) * 8 + (lane & 7);
    const int lcol = (lane >> 4) * 8;
    const int bh = blockIdx.y, b = bh / Hv, h = bh - b * Hv;
    const int q0 = blockIdx.x * 128;
    const int wm = w * 32;                // warp owns 32 q rows

    __half* Ks[3] = { sha, sha + 64 * ATP, sha + 2 * 64 * ATP };
    __half* Vs[3] = { sha + 3 * 64 * ATP, sha + 4 * 64 * ATP, sha + 5 * 64 * ATP };
    __half* Qs = sha + 6 * 64 * ATP;            // 128 x ATP
    float*  kb = (float*)(Qs + 128 * ATP);      // key bias [1024]

    const __half* qg = g_q + ((size_t)bh * Nv + q0) * HDv;
    const __half* kg = g_k + (size_t)bh * Nv * HDv;
    const __half* vg = g_v + (size_t)bh * HDv * Nv;   // [d][n]

    // Stage Q (128 x 64 halves)
    #pragma unroll
    for (int u = 0; u < 8; u++) {
        int idx = tid + 128 * u;
        int row = idx >> 3, q = idx & 7;
        cp16(smem_u32(Qs + row * ATP + q * 8), qg + (size_t)row * HDv + q * 8);
    }
    asm volatile("cp.async.commit_group;" ::: "memory");

    // Key bias: 0 valid, -1e5 masked (ex2 underflows to exact 0)
    #pragma unroll
    for (int u = 0; u < 8; u++) {
        int i = tid + 128 * u;
        kb[i] = maskg[b * Nv + i] ? 0.f : -1e5f;
    }

    auto load_kv = [&](int kt, int stg) {
        const __half* ktg = kg + (size_t)kt * 64 * HDv;
        const __half* vtg = vg + kt * 64;
        __half* Kd = Ks[stg];
        __half* Vd = Vs[stg];
        #pragma unroll
        for (int u = 0; u < 4; u++) {
            int idx = tid + 128 * u;
            int row = idx >> 3, q = idx & 7;
            cp16(smem_u32(Kd + row * ATP + q * 8), ktg + (size_t)row * HDv + q * 8);
            cp16(smem_u32(Vd + row * ATP + q * 8), vtg + (size_t)row * Nv + q * 8);
        }
        asm volatile("cp.async.commit_group;" ::: "memory");
    };
    load_kv(0, 0);
    load_kv(1, 1);

    asm volatile("cp.async.wait_group 2;" ::: "memory");
    __syncthreads();   // Q + kb visible

    // Q fragments via ldmatrix: qf[ks][mf*4 + r], mf = m16 block within m32
    uint32_t qf[4][8];
    {
        const uint32_t q32 = smem_u32(Qs);
        #pragma unroll
        for (int ks = 0; ks < 4; ks++)
            #pragma unroll
            for (int mf = 0; mf < 2; mf++)
                ldm_x4(&qf[ks][mf * 4],
                       q32 + ((wm + mf * 16 + lrow) * ATP + ks * 16 + lcol) * 2);
    }

    // Query rows owned by this thread (4): per mf block, rows lq and lq+8
    int  mrow[2][2], qv[2][2];
    #pragma unroll
    for (int mf = 0; mf < 2; mf++) {
        mrow[mf][0] = q0 + wm + mf * 16 + lq;
        mrow[mf][1] = mrow[mf][0] + 8;
        qv[mf][0] = maskg[b * Nv + mrow[mf][0]];
        qv[mf][1] = maskg[b * Nv + mrow[mf][1]];
    }

    float oc[2][8][4];                    // 64 accumulators (m32 x d64)
    #pragma unroll
    for (int mf = 0; mf < 2; mf++)
        #pragma unroll
        for (int df = 0; df < 8; df++)
            #pragma unroll
            for (int r = 0; r < 4; r++) oc[mf][df][r] = 0.f;
    float lsacc[2][4] = {{0.f,0.f,0.f,0.f},{0.f,0.f,0.f,0.f}};

    for (int kt = 0; kt < 16; kt++) {
        if (kt < 15) asm volatile("cp.async.wait_group 1;" ::: "memory");
        else         asm volatile("cp.async.wait_group 0;" ::: "memory");
        __syncthreads();
        if (kt + 2 < 16) load_kv(kt + 2, (kt + 2) % 3);

        const uint32_t kc32 = smem_u32(Ks[kt % 3]);
        const uint32_t vc32 = smem_u32(Vs[kt % 3]);
        const int k0g = kt * 64;

        // S = Q.K^T (m32 x n64), accumulator seeded with key bias
        float sc[2][8][4];
        #pragma unroll
        for (int nf = 0; nf < 8; nf++) {
            float2 kbv = *(const float2*)&kb[k0g + nf * 8 + 2 * lr4];
            #pragma unroll
            for (int mf = 0; mf < 2; mf++) {
                sc[mf][nf][0] = kbv.x; sc[mf][nf][1] = kbv.y;
                sc[mf][nf][2] = kbv.x; sc[mf][nf][3] = kbv.y;
            }
        }
        #pragma unroll
        for (int ks = 0; ks < 4; ks++) {
            #pragma unroll
            for (int j = 0; j < 4; j++) {
                uint32_t kq[4];
                ldm_x4(kq, kc32 + ((j * 16 + lrow) * ATP + ks * 16 + lcol) * 2);
                #pragma unroll
                for (int mf = 0; mf < 2; mf++) {
                    mma_f16(sc[mf][2 * j],     &qf[ks][mf * 4], kq[0], kq[2]);
                    mma_f16(sc[mf][2 * j + 1], &qf[ks][mf * 4], kq[1], kq[3]);
                }
            }
        }

        // softmax numerators on the MUFU pipe (in place)
        #pragma unroll
        for (int mf = 0; mf < 2; mf++)
            #pragma unroll
            for (int nf = 0; nf < 8; nf++)
                #pragma unroll
                for (int r = 0; r < 4; r++)
                    sc[mf][nf][r] = ex2(sc[mf][nf][r]);

        // O += P.V and lsacc += P.ones (P packed per-ks from registers)
        #pragma unroll
        for (int ks = 0; ks < 4; ks++) {
            uint32_t pa[2][4];
            #pragma unroll
            for (int mf = 0; mf < 2; mf++) {
                pa[mf][0] = h2u(__floats2half2_rn(sc[mf][2*ks][0],   sc[mf][2*ks][1]));
                pa[mf][1] = h2u(__floats2half2_rn(sc[mf][2*ks][2],   sc[mf][2*ks][3]));
                pa[mf][2] = h2u(__floats2half2_rn(sc[mf][2*ks+1][0], sc[mf][2*ks+1][1]));
                pa[mf][3] = h2u(__floats2half2_rn(sc[mf][2*ks+1][2], sc[mf][2*ks+1][3]));
            }
            #pragma unroll
            for (int j = 0; j < 4; j++) {
                uint32_t vq[4];
                ldm_x4(vq, vc32 + ((j * 16 + lrow) * ATP + ks * 16 + lcol) * 2);
                #pragma unroll
                for (int mf = 0; mf < 2; mf++) {
                    mma_f16(oc[mf][2 * j],     pa[mf], vq[0], vq[2]);
                    mma_f16(oc[mf][2 * j + 1], pa[mf], vq[1], vq[3]);
                }
            }
            #pragma unroll
            for (int mf = 0; mf < 2; mf++)
                mma_f16(lsacc[mf], pa[mf], ONES_H2, ONES_H2);
        }
    }

    // Epilogue per mf block: lsacc c0 = row lq sum, c2 = row lq+8 sum
    #pragma unroll
    for (int mf = 0; mf < 2; mf++) {
        const float inv0 = 1.f / lsacc[mf][0], inv1 = 1.f / lsacc[mf][2];
        __half* orow0 = g_o + ((size_t)b * Nv + mrow[mf][0]) * Dv + h * 64;
        __half* orow1 = g_o + ((size_t)b * Nv + mrow[mf][1]) * Dv + h * 64;
        #pragma unroll
        for (int df = 0; df < 8; df++) {
            const int cc = df * 8 + 2 * lr4;
            float2 v0, v1;
            if (qv[mf][0]) {
                v0 = make_float2(oc[mf][df][0] * inv0, oc[mf][df][1] * inv0);
            } else {
                v0 = make_float2(__half2float(vg[(size_t)cc * Nv + mrow[mf][0]]),
                                 __half2float(vg[(size_t)(cc + 1) * Nv + mrow[mf][0]]));
            }
            if (qv[mf][1]) {
                v1 = make_float2(oc[mf][df][2] * inv1, oc[mf][df][3] * inv1);
            } else {
                v1 = make_float2(__half2float(vg[(size_t)cc * Nv + mrow[mf][1]]),
                                 __half2float(vg[(size_t)(cc + 1) * Nv + mrow[mf][1]]));
            }
            *(uint32_t*)&orow0[cc] = h2u(__floats2half2_rn(v0.x, v0.y));
            *(uint32_t*)&orow1[cc] = h2u(__floats2half2_rn(v1.x, v1.y));
        }
    }
}

// ---------------------------------------------------------------------------
extern "C" void kernel_launch(void* const* d_in, const int* in_sizes, int n_in,
                              void* d_out, int out_size)
{
    const float* x     = (const float*)d_in[0];
    const int*   mask  = (const int*)d_in[1];
    const float* Wqkv  = (const float*)d_in[2];
    const float* Wproj = (const float*)d_in[3];
    const float* bproj = (const float*)d_in[4];
    float* out = (float*)d_out;
    (void)in_sizes; (void)n_in; (void)out_size;

    __half *p_xc, *p_wq, *p_wp, *p_o;
    cudaGetSymbolAddress((void**)&p_xc, g_xc);
    cudaGetSymbolAddress((void**)&p_wq, g_wq);
    cudaGetSymbolAddress((void**)&p_wp, g_wp);
    cudaGetSymbolAddress((void**)&p_o,  g_o);

    cudaFuncSetAttribute(gemm_mma<0>, cudaFuncAttributeMaxDynamicSharedMemorySize, GSMEM);
    cudaFuncSetAttribute(gemm_mma<1>, cudaFuncAttributeMaxDynamicSharedMemorySize, GSMEM);
    cudaFuncSetAttribute(attn_mma,    cudaFuncAttributeMaxDynamicSharedMemorySize, AT_SMEM);

    // Single merged prepass: fp32 -> fp16 (rne)
    cvt_all_k<<<(N4ALL + 255) / 256, 256>>>((const float4*)x, (const float4*)Wqkv,
                                            (const float4*)Wproj);

    // QKV projection (4-warp big-tile)
    dim3 g1(E3v / 128, Mv / 128);   // (18, 64)
    gemm_mma<0><<<g1, 128, GSMEM>>>(p_xc, p_wq, nullptr, nullptr);

    // Flash attention (4-warp big-tile)
    dim3 g2(Nv / 128, Bv * Hv);     // (8, 96)
    attn_mma<<<g2, 128, AT_SMEM>>>(mask);

    // Output projection
    dim3 g3(Dv / 128, Mv / 128);    // (6, 64)
    gemm_mma<1><<<g3, 128, GSMEM>>>(p_o, p_wp, bproj, out);
}

// round 12
// speedup vs baseline: 1.0190x; 1.0190x over previous
#include <cuda_runtime.h>
#include <cuda_fp16.h>
#include <cstdint>

#define Bv 8
#define Nv 1024
#define Dv 768
#define Hv 12
#define HDv 64
#define Mv (Bv*Nv)      /* 8192 */
#define E3v (3*Dv)      /* 2304 */

// folded into Q at QKV epilogue: 1/sqrt(64) * log2(e)
#define QSC 0.18033688011112042f

// Scratch (device globals, fp16)
__device__ __half g_q[Bv*Hv*Nv*HDv];   // [B*H][N][64], pre-scaled by QSC
__device__ __half g_k[Bv*Hv*Nv*HDv];   // [B*H][N][64]
__device__ __half g_v[Bv*Hv*Nv*HDv];   // [B*H][64][N]  (d-major)
__device__ __half g_o[Mv*Dv];          // [B][N][D]
__device__ __half g_xc[Mv*Dv];
__device__ __half g_wq[E3v*Dv];
__device__ __half g_wp[Dv*Dv];

// ============================================================================
// Helpers
// ============================================================================
__device__ __forceinline__ uint32_t smem_u32(const void* p) {
    uint32_t a;
    asm("{ .reg .u64 t; cvta.to.shared.u64 t, %1; cvt.u32.u64 %0, t; }"
        : "=r"(a) : "l"(p));
    return a;
}
__device__ __forceinline__ void cp16(uint32_t dst, const void* src) {
    asm volatile("cp.async.cg.shared.global [%0], [%1], 16;" :: "r"(dst), "l"(src));
}
__device__ __forceinline__ void ldm_x4(uint32_t r[4], uint32_t addr) {
    asm volatile("ldmatrix.sync.aligned.m8n8.x4.shared.b16 {%0,%1,%2,%3}, [%4];"
        : "=r"(r[0]), "=r"(r[1]), "=r"(r[2]), "=r"(r[3]) : "r"(addr));
}
__device__ __forceinline__ void mma_f16(float c[4], const uint32_t a[4],
                                        uint32_t b0, uint32_t b1) {
    asm volatile(
        "mma.sync.aligned.m16n8k16.row.col.f32.f16.f16.f32 "
        "{%0,%1,%2,%3}, {%4,%5,%6,%7}, {%8,%9}, {%0,%1,%2,%3};"
        : "+f"(c[0]), "+f"(c[1]), "+f"(c[2]), "+f"(c[3])
        : "r"(a[0]), "r"(a[1]), "r"(a[2]), "r"(a[3]), "r"(b0), "r"(b1));
}
// MUFU exp2 (2-ulp approx; underflows to 0 for large-negative inputs)
__device__ __forceinline__ float ex2(float d) {
    float r;
    asm("ex2.approx.f32 %0, %1;" : "=f"(r) : "f"(d));
    return r;
}
__device__ __forceinline__ uint32_t h2u(__half2 h) {
    return *reinterpret_cast<uint32_t*>(&h);
}

// ============================================================================
// Merged fp16 conversion prepass (x, Wqkv, Wproj)
// ============================================================================
#define N4X (Mv*Dv/4)
#define N4Q (E3v*Dv/4)
#define N4P (Dv*Dv/4)
#define N4ALL (N4X + N4Q + N4P)

__global__ void cvt_all_k(const float4* __restrict__ x,
                          const float4* __restrict__ wq,
                          const float4* __restrict__ wp)
{
    int i = blockIdx.x * 256 + threadIdx.x;
    if (i >= N4ALL) return;
    float4 v;
    uint2* d;
    if (i < N4X)            { v = x[i];                d = (uint2*)g_xc + i; }
    else if (i < N4X + N4Q) { v = wq[i - N4X];         d = (uint2*)g_wq + (i - N4X); }
    else                    { v = wp[i - N4X - N4Q];   d = (uint2*)g_wp + (i - N4X - N4Q); }
    *d = make_uint2(h2u(__floats2half2_rn(v.x, v.y)),
                    h2u(__floats2half2_rn(v.z, v.w)));
}

// ============================================================================
// fp16 mma.sync GEMM (NT): 128xTN tile, 256 threads / 8 warps,
// TN=128: warps 2x4 (warp 64x32);  TN=64: warps 4x2 (warp 32x32).
// K-chunk 64, 3-stage ring, one barrier per chunk, ldmatrix loads.
// MODE 0: A=g_xc, B=g_wq -> scatter into g_q (xQSC) / g_k / g_v(transposed)
// MODE 1: A=g_o,  B=g_wp -> out + bias (fp32)
// ============================================================================
#define KCH 64
#define NCH (Dv / KCH)               /* 12 */
#define LDPH 72                      /* pitch in halves (144B rows) */

template<int MODE, int TN>
__global__ __launch_bounds__(256, 2) void gemm_mma(
    const __half* __restrict__ A, const __half* __restrict__ Bw,
    const float* __restrict__ bias, float* __restrict__ out)
{
    constexpr int WMs  = (TN == 128) ? 2 : 4;   // warps along m
    constexpr int WMsz = 128 / WMs;             // 64 or 32
    constexpr int MF   = WMsz / 16;             // 4 or 2
    constexpr int ASTG = 128 * LDPH;            // A stage (halves)
    constexpr int BSTG = TN * LDPH;             // B stage (halves)
    constexpr int STGH = ASTG + BSTG;

    extern __shared__ __align__(16) __half shh[];
    const int tid = threadIdx.x;
    const int w = tid >> 5, lane = tid & 31;
    const int lq = lane >> 2, lr4 = lane & 3;
    const int lrow = ((lane >> 3) & 1) * 8 + (lane & 7);
    const int lcol = (lane >> 4) * 8;
    const int wm = (w % WMs) * WMsz;
    const int wn = (w / WMs) * 32;
    const int m0 = blockIdx.y * 128, e0 = blockIdx.x * TN;

    float c[MF][4][4];
    #pragma unroll
    for (int i = 0; i < MF; i++)
        #pragma unroll
        for (int j = 0; j < 4; j++)
            #pragma unroll
            for (int r = 0; r < 4; r++) c[i][j][r] = 0.f;

    auto load_st = [&](int ch, int stg) {
        __half* Ab = shh + stg * STGH;
        __half* Bb = Ab + ASTG;
        const __half* Ag = A + (size_t)m0 * Dv + ch * KCH;
        const __half* Bg = Bw + (size_t)e0 * Dv + ch * KCH;
        #pragma unroll
        for (int u = 0; u < 4; u++) {
            int idx = tid + 256 * u;          // 128 rows x 8 segs
            int row = idx >> 3, q = idx & 7;
            cp16(smem_u32(Ab + row * LDPH + q * 8), Ag + (size_t)row * Dv + q * 8);
        }
        #pragma unroll
        for (int u = 0; u < TN / 32; u++) {   // TN rows x 8 segs
            int idx = tid + 256 * u;
            int row = idx >> 3, q = idx & 7;
            cp16(smem_u32(Bb + row * LDPH + q * 8), Bg + (size_t)row * Dv + q * 8);
        }
        asm volatile("cp.async.commit_group;" ::: "memory");
    };

    load_st(0, 0);
    load_st(1, 1);

    for (int ch = 0; ch < NCH; ch++) {
        if (ch < NCH - 1)
            asm volatile("cp.async.wait_group 1;" ::: "memory");
        else
            asm volatile("cp.async.wait_group 0;" ::: "memory");
        __syncthreads();
        if (ch + 2 < NCH) load_st(ch + 2, (ch + 2) % 3);

        const uint32_t ab32 = smem_u32(shh + (ch % 3) * STGH);
        const uint32_t bb32 = ab32 + ASTG * 2;

        #pragma unroll
        for (int kk = 0; kk < 4; kk++) {
            uint32_t af[MF][4];
            #pragma unroll
            for (int mf = 0; mf < MF; mf++)
                ldm_x4(af[mf], ab32 + ((wm + mf * 16 + lrow) * LDPH + kk * 16 + lcol) * 2);
            uint32_t bq[2][4];
            #pragma unroll
            for (int j = 0; j < 2; j++)
                ldm_x4(bq[j], bb32 + ((wn + j * 16 + lrow) * LDPH + kk * 16 + lcol) * 2);
            #pragma unroll
            for (int mf = 0; mf < MF; mf++) {
                mma_f16(c[mf][0], af[mf], bq[0][0], bq[0][2]);
                mma_f16(c[mf][1], af[mf], bq[0][1], bq[0][3]);
                mma_f16(c[mf][2], af[mf], bq[1][0], bq[1][2]);
                mma_f16(c[mf][3], af[mf], bq[1][1], bq[1][3]);
            }
        }
    }

    // Epilogue
    #pragma unroll
    for (int nf = 0; nf < 4; nf++) {
        const int e = e0 + wn + nf * 8 + lr4 * 2;
        #pragma unroll
        for (int mf = 0; mf < MF; mf++) {
            #pragma unroll
            for (int half = 0; half < 2; half++) {
                const int m = m0 + wm + mf * 16 + lq + half * 8;
                float2 v = make_float2(c[mf][nf][half * 2], c[mf][nf][half * 2 + 1]);
                if (MODE == 0) {
                    const int b = m >> 10, n = m & 1023;
                    const int s = e / Dv, r = e - s * Dv;
                    const int hh = r >> 6, i2 = r & 63;
                    if (s == 0) { v.x *= QSC; v.y *= QSC; }
                    if (s < 2) {
                        __half* dst = ((s == 0) ? g_q : g_k)
                                    + (((size_t)(b * Hv + hh)) * Nv + n) * HDv + i2;
                        *(uint32_t*)dst = h2u(__floats2half2_rn(v.x, v.y));
                    } else {
                        __half* dst = g_v + ((size_t)(b * Hv + hh)) * HDv * Nv
                                    + (size_t)i2 * Nv + n;
                        dst[0]  = __float2half_rn(v.x);
                        dst[Nv] = __float2half_rn(v.y);
                    }
                } else {
                    v.x += bias[e];
                    v.y += bias[e + 1];
                    *(float2*)(out + (size_t)m * Dv + e) = v;
                }
            }
        }
    }
}

#define GSMEM0 (3 * (128 + 128) * LDPH * 2)   /* 110592 */
#define GSMEM1 (3 * (128 + 64)  * LDPH * 2)   /* 82944  */

// ============================================================================
// fp16 mma.sync flash attention (R10 config): 256 threads / 8 warps x m16,
// no-max softmax via MUFU ex2, P in registers, row sums via tensor core,
// 3-stage KV ring, one barrier per kv tile. CTA = (bh, 128-row q tile).
// ============================================================================
#define ATP 72
#define AT_SMEM ((3*64*ATP*2 + 128*ATP) * 2 + Nv * 4)   /* 77824 */
#define ONES_H2 0x3C003C00u   /* __half2(1,1) */

__global__ __launch_bounds__(256, 2) void attn_mma(const int* __restrict__ maskg)
{
    extern __shared__ __align__(16) __half sha[];

    const int tid = threadIdx.x;
    const int w = tid >> 5, lane = tid & 31;
    const int lq = lane >> 2, lr4 = lane & 3;
    const int lrow = ((lane >> 3) & 1) * 8 + (lane & 7);
    const int lcol = (lane >> 4) * 8;
    const int bh = blockIdx.y, b = bh / Hv, h = bh - b * Hv;
    const int q0 = blockIdx.x * 128;
    const int wm = w * 16;

    __half* Ks[3] = { sha, sha + 64 * ATP, sha + 2 * 64 * ATP };
    __half* Vs[3] = { sha + 3 * 64 * ATP, sha + 4 * 64 * ATP, sha + 5 * 64 * ATP };
    __half* Qs = sha + 6 * 64 * ATP;            // 128 x ATP
    float*  kb = (float*)(Qs + 128 * ATP);      // key bias [1024]

    const __half* qg = g_q + ((size_t)bh * Nv + q0) * HDv;
    const __half* kg = g_k + (size_t)bh * Nv * HDv;
    const __half* vg = g_v + (size_t)bh * HDv * Nv;   // [d][n]

    // Stage Q (128 x 64 halves)
    #pragma unroll
    for (int u = 0; u < 4; u++) {
        int idx = tid + 256 * u;
        int row = idx >> 3, q = idx & 7;
        cp16(smem_u32(Qs + row * ATP + q * 8), qg + (size_t)row * HDv + q * 8);
    }
    asm volatile("cp.async.commit_group;" ::: "memory");

    // Key bias: 0 valid, -1e5 masked (ex2 underflows to exact 0)
    #pragma unroll
    for (int u = 0; u < 4; u++) {
        int i = tid + 256 * u;
        kb[i] = maskg[b * Nv + i] ? 0.f : -1e5f;
    }

    auto load_kv = [&](int kt, int stg) {
        const __half* ktg = kg + (size_t)kt * 64 * HDv;
        const __half* vtg = vg + kt * 64;
        __half* Kd = Ks[stg];
        __half* Vd = Vs[stg];
        #pragma unroll
        for (int u = 0; u < 2; u++) {
            int idx = tid + 256 * u;
            int row = idx >> 3, q = idx & 7;
            cp16(smem_u32(Kd + row * ATP + q * 8), ktg + (size_t)row * HDv + q * 8);
            cp16(smem_u32(Vd + row * ATP + q * 8), vtg + (size_t)row * Nv + q * 8);
        }
        asm volatile("cp.async.commit_group;" ::: "memory");
    };
    load_kv(0, 0);
    load_kv(1, 1);

    asm volatile("cp.async.wait_group 2;" ::: "memory");
    __syncthreads();   // Q + kb visible

    // Q fragments via ldmatrix (pre-scaled by QSC)
    uint32_t qf[4][4];
    {
        const uint32_t q32 = smem_u32(Qs);
        #pragma unroll
        for (int ks = 0; ks < 4; ks++)
            ldm_x4(qf[ks], q32 + ((wm + lrow) * ATP + ks * 16 + lcol) * 2);
    }

    const int mrow0 = q0 + wm + lq, mrow1 = mrow0 + 8;
    const int qv0 = maskg[b * Nv + mrow0];
    const int qv1 = maskg[b * Nv + mrow1];

    float oc[8][4];
    #pragma unroll
    for (int df = 0; df < 8; df++)
        #pragma unroll
        for (int r = 0; r < 4; r++) oc[df][r] = 0.f;
    float lsacc[4] = {0.f, 0.f, 0.f, 0.f};   // row sums via P x ones MMA

    for (int kt = 0; kt < 16; kt++) {
        if (kt < 15) asm volatile("cp.async.wait_group 1;" ::: "memory");
        else         asm volatile("cp.async.wait_group 0;" ::: "memory");
        __syncthreads();
        if (kt + 2 < 16) load_kv(kt + 2, (kt + 2) % 3);

        const uint32_t kc32 = smem_u32(Ks[kt % 3]);
        const uint32_t vc32 = smem_u32(Vs[kt % 3]);
        const int k0g = kt * 64;

        // S = Q.K^T, accumulator seeded with key bias
        float sc[8][4];
        #pragma unroll
        for (int nf = 0; nf < 8; nf++) {
            float2 kbv = *(const float2*)&kb[k0g + nf * 8 + 2 * lr4];
            sc[nf][0] = kbv.x; sc[nf][1] = kbv.y;
            sc[nf][2] = kbv.x; sc[nf][3] = kbv.y;
        }
        #pragma unroll
        for (int ks = 0; ks < 4; ks++) {
            #pragma unroll
            for (int j = 0; j < 4; j++) {
                uint32_t kq[4];
                ldm_x4(kq, kc32 + ((j * 16 + lrow) * ATP + ks * 16 + lcol) * 2);
                mma_f16(sc[2 * j],     qf[ks], kq[0], kq[2]);
                mma_f16(sc[2 * j + 1], qf[ks], kq[1], kq[3]);
            }
        }

        // softmax numerators: p = 2^s on the MUFU pipe, packed to A-fragments
        uint32_t ph[8][2];
        #pragma unroll
        for (int nf = 0; nf < 8; nf++) {
            ph[nf][0] = h2u(__floats2half2_rn(ex2(sc[nf][0]), ex2(sc[nf][1])));
            ph[nf][1] = h2u(__floats2half2_rn(ex2(sc[nf][2]), ex2(sc[nf][3])));
        }

        // O += P.V  and  lsacc += P.ones (row sums on the tensor pipe)
        #pragma unroll
        for (int ks = 0; ks < 4; ks++) {
            uint32_t pa[4] = { ph[2 * ks][0],     ph[2 * ks][1],
                               ph[2 * ks + 1][0], ph[2 * ks + 1][1] };
            #pragma unroll
            for (int j = 0; j < 4; j++) {
                uint32_t vq[4];
                ldm_x4(vq, vc32 + ((j * 16 + lrow) * ATP + ks * 16 + lcol) * 2);
                mma_f16(oc[2 * j],     pa, vq[0], vq[2]);
                mma_f16(oc[2 * j + 1], pa, vq[1], vq[3]);
            }
            mma_f16(lsacc, pa, ONES_H2, ONES_H2);
        }
    }

    // lsacc: every column holds the row sum -> c0 = row lq, c2 = row lq+8
    const float inv0 = 1.f / lsacc[0], inv1 = 1.f / lsacc[2];

    // Epilogue: valid rows -> oc/l; invalid rows -> V[:, row]
    __half* orow0 = g_o + ((size_t)b * Nv + mrow0) * Dv + h * 64;
    __half* orow1 = g_o + ((size_t)b * Nv + mrow1) * Dv + h * 64;
    #pragma unroll
    for (int df = 0; df < 8; df++) {
        const int cc = df * 8 + 2 * lr4;
        float2 v0, v1;
        if (qv0) {
            v0 = make_float2(oc[df][0] * inv0, oc[df][1] * inv0);
        } else {
            v0 = make_float2(__half2float(vg[(size_t)cc * Nv + mrow0]),
                             __half2float(vg[(size_t)(cc + 1) * Nv + mrow0]));
        }
        if (qv1) {
            v1 = make_float2(oc[df][2] * inv1, oc[df][3] * inv1);
        } else {
            v1 = make_float2(__half2float(vg[(size_t)cc * Nv + mrow1]),
                             __half2float(vg[(size_t)(cc + 1) * Nv + mrow1]));
        }
        *(uint32_t*)&orow0[cc] = h2u(__floats2half2_rn(v0.x, v0.y));
        *(uint32_t*)&orow1[cc] = h2u(__floats2half2_rn(v1.x, v1.y));
    }
}

// ---------------------------------------------------------------------------
extern "C" void kernel_launch(void* const* d_in, const int* in_sizes, int n_in,
                              void* d_out, int out_size)
{
    const float* x     = (const float*)d_in[0];
    const int*   mask  = (const int*)d_in[1];
    const float* Wqkv  = (const float*)d_in[2];
    const float* Wproj = (const float*)d_in[3];
    const float* bproj = (const float*)d_in[4];
    float* out = (float*)d_out;
    (void)in_sizes; (void)n_in; (void)out_size;

    __half *p_xc, *p_wq, *p_wp, *p_o;
    cudaGetSymbolAddress((void**)&p_xc, g_xc);
    cudaGetSymbolAddress((void**)&p_wq, g_wq);
    cudaGetSymbolAddress((void**)&p_wp, g_wp);
    cudaGetSymbolAddress((void**)&p_o,  g_o);

    cudaFuncSetAttribute((const void*)gemm_mma<0,128>,
                         cudaFuncAttributeMaxDynamicSharedMemorySize, GSMEM0);
    cudaFuncSetAttribute((const void*)gemm_mma<1,64>,
                         cudaFuncAttributeMaxDynamicSharedMemorySize, GSMEM1);
    cudaFuncSetAttribute((const void*)attn_mma,
                         cudaFuncAttributeMaxDynamicSharedMemorySize, AT_SMEM);

    // Single merged prepass: fp32 -> fp16 (rne)
    cvt_all_k<<<(N4ALL + 255) / 256, 256>>>((const float4*)x, (const float4*)Wqkv,
                                            (const float4*)Wproj);

    // QKV projection (128x128 tiles, 3.9 waves)
    dim3 g1(E3v / 128, Mv / 128);   // (18, 64)
    gemm_mma<0,128><<<g1, 256, GSMEM0>>>(p_xc, p_wq, nullptr, nullptr);

    // Flash attention
    dim3 g2(Nv / 128, Bv * Hv);     // (8, 96)
    attn_mma<<<g2, 256, AT_SMEM>>>(mask);

    // Output projection (128x64 tiles -> 768 CTAs, kills the 1.3-wave tail)
    dim3 g3(Dv / 64, Mv / 128);     // (12, 64)
    gemm_mma<1,64><<<g3, 256, GSMEM1>>>(p_o, p_wp, bproj, out);
}

// round 13
// speedup vs baseline: 1.0508x; 1.0312x over previous
#include <cuda_runtime.h>
#include <cuda_fp16.h>
#include <cstdint>

#define Bv 8
#define Nv 1024
#define Dv 768
#define Hv 12
#define HDv 64
#define Mv (Bv*Nv)      /* 8192 */
#define E3v (3*Dv)      /* 2304 */

// folded into Q at QKV epilogue: 1/sqrt(64) * log2(e)
#define QSC 0.18033688011112042f

// Scratch (device globals, fp16) — Q, K, V all [B*H][N][64] row-major
__device__ __half g_q[Bv*Hv*Nv*HDv];   // pre-scaled by QSC
__device__ __half g_k[Bv*Hv*Nv*HDv];
__device__ __half g_v[Bv*Hv*Nv*HDv];   // row-major; transposed in-attn via ldmatrix.trans
__device__ __half g_o[Mv*Dv];          // [B][N][D]
__device__ __half g_xc[Mv*Dv];
__device__ __half g_wq[E3v*Dv];
__device__ __half g_wp[Dv*Dv];

// ============================================================================
// Helpers
// ============================================================================
__device__ __forceinline__ uint32_t smem_u32(const void* p) {
    uint32_t a;
    asm("{ .reg .u64 t; cvta.to.shared.u64 t, %1; cvt.u32.u64 %0, t; }"
        : "=r"(a) : "l"(p));
    return a;
}
__device__ __forceinline__ void cp16(uint32_t dst, const void* src) {
    asm volatile("cp.async.cg.shared.global [%0], [%1], 16;" :: "r"(dst), "l"(src));
}
__device__ __forceinline__ void ldm_x4(uint32_t r[4], uint32_t addr) {
    asm volatile("ldmatrix.sync.aligned.m8n8.x4.shared.b16 {%0,%1,%2,%3}, [%4];"
        : "=r"(r[0]), "=r"(r[1]), "=r"(r[2]), "=r"(r[3]) : "r"(addr));
}
__device__ __forceinline__ void ldm_x4_t(uint32_t r[4], uint32_t addr) {
    asm volatile("ldmatrix.sync.aligned.m8n8.x4.trans.shared.b16 {%0,%1,%2,%3}, [%4];"
        : "=r"(r[0]), "=r"(r[1]), "=r"(r[2]), "=r"(r[3]) : "r"(addr));
}
__device__ __forceinline__ void mma_f16(float c[4], const uint32_t a[4],
                                        uint32_t b0, uint32_t b1) {
    asm volatile(
        "mma.sync.aligned.m16n8k16.row.col.f32.f16.f16.f32 "
        "{%0,%1,%2,%3}, {%4,%5,%6,%7}, {%8,%9}, {%0,%1,%2,%3};"
        : "+f"(c[0]), "+f"(c[1]), "+f"(c[2]), "+f"(c[3])
        : "r"(a[0]), "r"(a[1]), "r"(a[2]), "r"(a[3]), "r"(b0), "r"(b1));
}
// MUFU exp2 (2-ulp approx; underflows to 0 for large-negative inputs)
__device__ __forceinline__ float ex2(float d) {
    float r;
    asm("ex2.approx.f32 %0, %1;" : "=f"(r) : "f"(d));
    return r;
}
__device__ __forceinline__ uint32_t h2u(__half2 h) {
    return *reinterpret_cast<uint32_t*>(&h);
}

// ============================================================================
// Merged fp16 conversion prepass (x, Wqkv, Wproj)
// ============================================================================
#define N4X (Mv*Dv/4)
#define N4Q (E3v*Dv/4)
#define N4P (Dv*Dv/4)
#define N4ALL (N4X + N4Q + N4P)

__global__ void cvt_all_k(const float4* __restrict__ x,
                          const float4* __restrict__ wq,
                          const float4* __restrict__ wp)
{
    int i = blockIdx.x * 256 + threadIdx.x;
    if (i >= N4ALL) return;
    float4 v;
    uint2* d;
    if (i < N4X)            { v = x[i];                d = (uint2*)g_xc + i; }
    else if (i < N4X + N4Q) { v = wq[i - N4X];         d = (uint2*)g_wq + (i - N4X); }
    else                    { v = wp[i - N4X - N4Q];   d = (uint2*)g_wp + (i - N4X - N4Q); }
    *d = make_uint2(h2u(__floats2half2_rn(v.x, v.y)),
                    h2u(__floats2half2_rn(v.z, v.w)));
}

// ============================================================================
// fp16 mma.sync GEMM (NT): 128xTN tile, 256 threads / 8 warps,
// TN=128: warps 2x4 (warp 64x32);  TN=64: warps 4x2 (warp 32x32).
// K-chunk 64, 3-stage ring, one barrier per chunk, ldmatrix loads.
// MODE 0: A=g_xc, B=g_wq -> coalesced stores into g_q (xQSC) / g_k / g_v
// MODE 1: A=g_o,  B=g_wp -> out + bias (fp32)
// ============================================================================
#define KCH 64
#define NCH (Dv / KCH)               /* 12 */
#define LDPH 72                      /* pitch in halves (144B rows) */

template<int MODE, int TN>
__global__ __launch_bounds__(256, 2) void gemm_mma(
    const __half* __restrict__ A, const __half* __restrict__ Bw,
    const float* __restrict__ bias, float* __restrict__ out)
{
    constexpr int WMs  = (TN == 128) ? 2 : 4;
    constexpr int WMsz = 128 / WMs;
    constexpr int MF   = WMsz / 16;
    constexpr int ASTG = 128 * LDPH;
    constexpr int BSTG = TN * LDPH;
    constexpr int STGH = ASTG + BSTG;

    extern __shared__ __align__(16) __half shh[];
    const int tid = threadIdx.x;
    const int w = tid >> 5, lane = tid & 31;
    const int lq = lane >> 2, lr4 = lane & 3;
    const int lrow = ((lane >> 3) & 1) * 8 + (lane & 7);
    const int lcol = (lane >> 4) * 8;
    const int wm = (w % WMs) * WMsz;
    const int wn = (w / WMs) * 32;
    const int m0 = blockIdx.y * 128, e0 = blockIdx.x * TN;

    float c[MF][4][4];
    #pragma unroll
    for (int i = 0; i < MF; i++)
        #pragma unroll
        for (int j = 0; j < 4; j++)
            #pragma unroll
            for (int r = 0; r < 4; r++) c[i][j][r] = 0.f;

    auto load_st = [&](int ch, int stg) {
        __half* Ab = shh + stg * STGH;
        __half* Bb = Ab + ASTG;
        const __half* Ag = A + (size_t)m0 * Dv + ch * KCH;
        const __half* Bg = Bw + (size_t)e0 * Dv + ch * KCH;
        #pragma unroll
        for (int u = 0; u < 4; u++) {
            int idx = tid + 256 * u;
            int row = idx >> 3, q = idx & 7;
            cp16(smem_u32(Ab + row * LDPH + q * 8), Ag + (size_t)row * Dv + q * 8);
        }
        #pragma unroll
        for (int u = 0; u < TN / 32; u++) {
            int idx = tid + 256 * u;
            int row = idx >> 3, q = idx & 7;
            cp16(smem_u32(Bb + row * LDPH + q * 8), Bg + (size_t)row * Dv + q * 8);
        }
        asm volatile("cp.async.commit_group;" ::: "memory");
    };

    load_st(0, 0);
    load_st(1, 1);

    for (int ch = 0; ch < NCH; ch++) {
        if (ch < NCH - 1)
            asm volatile("cp.async.wait_group 1;" ::: "memory");
        else
            asm volatile("cp.async.wait_group 0;" ::: "memory");
        __syncthreads();
        if (ch + 2 < NCH) load_st(ch + 2, (ch + 2) % 3);

        const uint32_t ab32 = smem_u32(shh + (ch % 3) * STGH);
        const uint32_t bb32 = ab32 + ASTG * 2;

        #pragma unroll
        for (int kk = 0; kk < 4; kk++) {
            uint32_t af[MF][4];
            #pragma unroll
            for (int mf = 0; mf < MF; mf++)
                ldm_x4(af[mf], ab32 + ((wm + mf * 16 + lrow) * LDPH + kk * 16 + lcol) * 2);
            uint32_t bq[2][4];
            #pragma unroll
            for (int j = 0; j < 2; j++)
                ldm_x4(bq[j], bb32 + ((wn + j * 16 + lrow) * LDPH + kk * 16 + lcol) * 2);
            #pragma unroll
            for (int mf = 0; mf < MF; mf++) {
                mma_f16(c[mf][0], af[mf], bq[0][0], bq[0][2]);
                mma_f16(c[mf][1], af[mf], bq[0][1], bq[0][3]);
                mma_f16(c[mf][2], af[mf], bq[1][0], bq[1][2]);
                mma_f16(c[mf][3], af[mf], bq[1][1], bq[1][3]);
            }
        }
    }

    // Epilogue (MODE 0: all of Q/K/V coalesced row-major uint32 stores)
    #pragma unroll
    for (int nf = 0; nf < 4; nf++) {
        const int e = e0 + wn + nf * 8 + lr4 * 2;
        #pragma unroll
        for (int mf = 0; mf < MF; mf++) {
            #pragma unroll
            for (int half = 0; half < 2; half++) {
                const int m = m0 + wm + mf * 16 + lq + half * 8;
                float2 v = make_float2(c[mf][nf][half * 2], c[mf][nf][half * 2 + 1]);
                if (MODE == 0) {
                    const int b = m >> 10, n = m & 1023;
                    const int s = e / Dv, r = e - s * Dv;
                    const int hh = r >> 6, i2 = r & 63;
                    if (s == 0) { v.x *= QSC; v.y *= QSC; }
                    __half* dst = ((s == 0) ? g_q : (s == 1 ? g_k : g_v))
                                + (((size_t)(b * Hv + hh)) * Nv + n) * HDv + i2;
                    *(uint32_t*)dst = h2u(__floats2half2_rn(v.x, v.y));
                } else {
                    v.x += bias[e];
                    v.y += bias[e + 1];
                    *(float2*)(out + (size_t)m * Dv + e) = v;
                }
            }
        }
    }
}

#define GSMEM0 (3 * (128 + 128) * LDPH * 2)   /* 110592 */
#define GSMEM1 (3 * (128 + 64)  * LDPH * 2)   /* 82944  */

// ============================================================================
// fp16 mma.sync flash attention: 256 threads / 8 warps x m16,
// no-max softmax via MUFU ex2, P in registers, row sums via tensor core,
// 3-stage KV ring, V row-major + ldmatrix.trans for the PV B-fragments.
// CTA = (bh, 128-row q tile).
// ============================================================================
#define ATP 72
#define AT_SMEM ((3*64*ATP*2 + 128*ATP) * 2 + Nv * 4)   /* 77824 */
#define ONES_H2 0x3C003C00u   /* __half2(1,1) */

__global__ __launch_bounds__(256, 2) void attn_mma(const int* __restrict__ maskg)
{
    extern __shared__ __align__(16) __half sha[];

    const int tid = threadIdx.x;
    const int w = tid >> 5, lane = tid & 31;
    const int lq = lane >> 2, lr4 = lane & 3;
    const int lrow = ((lane >> 3) & 1) * 8 + (lane & 7);
    const int lcol = (lane >> 4) * 8;
    const int bh = blockIdx.y, b = bh / Hv, h = bh - b * Hv;
    const int q0 = blockIdx.x * 128;
    const int wm = w * 16;

    __half* Ks[3] = { sha, sha + 64 * ATP, sha + 2 * 64 * ATP };
    __half* Vs[3] = { sha + 3 * 64 * ATP, sha + 4 * 64 * ATP, sha + 5 * 64 * ATP };
    __half* Qs = sha + 6 * 64 * ATP;            // 128 x ATP
    float*  kb = (float*)(Qs + 128 * ATP);      // key bias [1024]

    const __half* qg = g_q + ((size_t)bh * Nv + q0) * HDv;
    const __half* kg = g_k + (size_t)bh * Nv * HDv;
    const __half* vg = g_v + (size_t)bh * Nv * HDv;   // row-major [n][d]

    // Stage Q (128 x 64 halves)
    #pragma unroll
    for (int u = 0; u < 4; u++) {
        int idx = tid + 256 * u;
        int row = idx >> 3, q = idx & 7;
        cp16(smem_u32(Qs + row * ATP + q * 8), qg + (size_t)row * HDv + q * 8);
    }
    asm volatile("cp.async.commit_group;" ::: "memory");

    // Key bias: 0 valid, -1e5 masked (ex2 underflows to exact 0)
    #pragma unroll
    for (int u = 0; u < 4; u++) {
        int i = tid + 256 * u;
        kb[i] = maskg[b * Nv + i] ? 0.f : -1e5f;
    }

    auto load_kv = [&](int kt, int stg) {
        const __half* ktg = kg + (size_t)kt * 64 * HDv;
        const __half* vtg = vg + (size_t)kt * 64 * HDv;
        __half* Kd = Ks[stg];
        __half* Vd = Vs[stg];
        #pragma unroll
        for (int u = 0; u < 2; u++) {
            int idx = tid + 256 * u;
            int row = idx >> 3, q = idx & 7;
            cp16(smem_u32(Kd + row * ATP + q * 8), ktg + (size_t)row * HDv + q * 8);
            cp16(smem_u32(Vd + row * ATP + q * 8), vtg + (size_t)row * HDv + q * 8);
        }
        asm volatile("cp.async.commit_group;" ::: "memory");
    };
    load_kv(0, 0);
    load_kv(1, 1);

    asm volatile("cp.async.wait_group 2;" ::: "memory");
    __syncthreads();   // Q + kb visible

    // Q fragments via ldmatrix (pre-scaled by QSC)
    uint32_t qf[4][4];
    {
        const uint32_t q32 = smem_u32(Qs);
        #pragma unroll
        for (int ks = 0; ks < 4; ks++)
            ldm_x4(qf[ks], q32 + ((wm + lrow) * ATP + ks * 16 + lcol) * 2);
    }

    const int mrow0 = q0 + wm + lq, mrow1 = mrow0 + 8;
    const int qv0 = maskg[b * Nv + mrow0];
    const int qv1 = maskg[b * Nv + mrow1];

    float oc[8][4];
    #pragma unroll
    for (int df = 0; df < 8; df++)
        #pragma unroll
        for (int r = 0; r < 4; r++) oc[df][r] = 0.f;
    float lsacc[4] = {0.f, 0.f, 0.f, 0.f};   // row sums via P x ones MMA

    for (int kt = 0; kt < 16; kt++) {
        if (kt < 15) asm volatile("cp.async.wait_group 1;" ::: "memory");
        else         asm volatile("cp.async.wait_group 0;" ::: "memory");
        __syncthreads();
        if (kt + 2 < 16) load_kv(kt + 2, (kt + 2) % 3);

        const uint32_t kc32 = smem_u32(Ks[kt % 3]);
        const uint32_t vc32 = smem_u32(Vs[kt % 3]);
        const int k0g = kt * 64;

        // S = Q.K^T, accumulator seeded with key bias
        float sc[8][4];
        #pragma unroll
        for (int nf = 0; nf < 8; nf++) {
            float2 kbv = *(const float2*)&kb[k0g + nf * 8 + 2 * lr4];
            sc[nf][0] = kbv.x; sc[nf][1] = kbv.y;
            sc[nf][2] = kbv.x; sc[nf][3] = kbv.y;
        }
        #pragma unroll
        for (int ks = 0; ks < 4; ks++) {
            #pragma unroll
            for (int j = 0; j < 4; j++) {
                uint32_t kq[4];
                ldm_x4(kq, kc32 + ((j * 16 + lrow) * ATP + ks * 16 + lcol) * 2);
                mma_f16(sc[2 * j],     qf[ks], kq[0], kq[2]);
                mma_f16(sc[2 * j + 1], qf[ks], kq[1], kq[3]);
            }
        }

        // softmax numerators: p = 2^s on the MUFU pipe, packed to A-fragments
        uint32_t ph[8][2];
        #pragma unroll
        for (int nf = 0; nf < 8; nf++) {
            ph[nf][0] = h2u(__floats2half2_rn(ex2(sc[nf][0]), ex2(sc[nf][1])));
            ph[nf][1] = h2u(__floats2half2_rn(ex2(sc[nf][2]), ex2(sc[nf][3])));
        }

        // O += P.V  and  lsacc += P.ones
        // V tile is row-major [key][d]; ldmatrix.trans delivers B-fragments:
        // mats = {k0-7/d0-7, k8-15/d0-7, k0-7/d8-15, k8-15/d8-15}
        #pragma unroll
        for (int ks = 0; ks < 4; ks++) {
            uint32_t pa[4] = { ph[2 * ks][0],     ph[2 * ks][1],
                               ph[2 * ks + 1][0], ph[2 * ks + 1][1] };
            #pragma unroll
            for (int j = 0; j < 4; j++) {
                uint32_t vq[4];
                ldm_x4_t(vq, vc32 + ((ks * 16 + lrow) * ATP + j * 16 + lcol) * 2);
                mma_f16(oc[2 * j],     pa, vq[0], vq[1]);
                mma_f16(oc[2 * j + 1], pa, vq[2], vq[3]);
            }
            mma_f16(lsacc, pa, ONES_H2, ONES_H2);
        }
    }

    // lsacc: every column holds the row sum -> c0 = row lq, c2 = row lq+8
    const float inv0 = 1.f / lsacc[0], inv1 = 1.f / lsacc[2];

    // Epilogue: valid rows -> oc/l; invalid rows -> V[row] (row-major now)
    __half* orow0 = g_o + ((size_t)b * Nv + mrow0) * Dv + h * 64;
    __half* orow1 = g_o + ((size_t)b * Nv + mrow1) * Dv + h * 64;
    #pragma unroll
    for (int df = 0; df < 8; df++) {
        const int cc = df * 8 + 2 * lr4;
        float2 v0, v1;
        if (qv0) {
            v0 = make_float2(oc[df][0] * inv0, oc[df][1] * inv0);
        } else {
            __half2 hv = *(const __half2*)&vg[(size_t)mrow0 * HDv + cc];
            v0 = make_float2(__half2float(hv.x), __half2float(hv.y));
        }
        if (qv1) {
            v1 = make_float2(oc[df][2] * inv1, oc[df][3] * inv1);
        } else {
            __half2 hv = *(const __half2*)&vg[(size_t)mrow1 * HDv + cc];
            v1 = make_float2(__half2float(hv.x), __half2float(hv.y));
        }
        *(uint32_t*)&orow0[cc] = h2u(__floats2half2_rn(v0.x, v0.y));
        *(uint32_t*)&orow1[cc] = h2u(__floats2half2_rn(v1.x, v1.y));
    }
}

// ---------------------------------------------------------------------------
extern "C" void kernel_launch(void* const* d_in, const int* in_sizes, int n_in,
                              void* d_out, int out_size)
{
    const float* x     = (const float*)d_in[0];
    const int*   mask  = (const int*)d_in[1];
    const float* Wqkv  = (const float*)d_in[2];
    const float* Wproj = (const float*)d_in[3];
    const float* bproj = (const float*)d_in[4];
    float* out = (float*)d_out;
    (void)in_sizes; (void)n_in; (void)out_size;

    __half *p_xc, *p_wq, *p_wp, *p_o;
    cudaGetSymbolAddress((void**)&p_xc, g_xc);
    cudaGetSymbolAddress((void**)&p_wq, g_wq);
    cudaGetSymbolAddress((void**)&p_wp, g_wp);
    cudaGetSymbolAddress((void**)&p_o,  g_o);

    cudaFuncSetAttribute((const void*)gemm_mma<0,128>,
                         cudaFuncAttributeMaxDynamicSharedMemorySize, GSMEM0);
    cudaFuncSetAttribute((const void*)gemm_mma<1,64>,
                         cudaFuncAttributeMaxDynamicSharedMemorySize, GSMEM1);
    cudaFuncSetAttribute((const void*)attn_mma,
                         cudaFuncAttributeMaxDynamicSharedMemorySize, AT_SMEM);

    // Single merged prepass: fp32 -> fp16 (rne)
    cvt_all_k<<<(N4ALL + 255) / 256, 256>>>((const float4*)x, (const float4*)Wqkv,
                                            (const float4*)Wproj);

    // QKV projection (coalesced Q/K/V stores)
    dim3 g1(E3v / 128, Mv / 128);   // (18, 64)
    gemm_mma<0,128><<<g1, 256, GSMEM0>>>(p_xc, p_wq, nullptr, nullptr);

    // Flash attention (V transposed in-kernel via ldmatrix.trans)
    dim3 g2(Nv / 128, Bv * Hv);     // (8, 96)
    attn_mma<<<g2, 256, AT_SMEM>>>(mask);

    // Output projection
    dim3 g3(Dv / 64, Mv / 128);     // (12, 64)
    gemm_mma<1,64><<<g3, 256, GSMEM1>>>(p_o, p_wp, bproj, out);
}

// round 14
// speedup vs baseline: 1.0535x; 1.0026x over previous
#include <cuda_runtime.h>
#include <cuda_fp16.h>
#include <cstdint>

#define Bv 8
#define Nv 1024
#define Dv 768
#define Hv 12
#define HDv 64
#define Mv (Bv*Nv)      /* 8192 */
#define E3v (3*Dv)      /* 2304 */

// folded into Q at QKV epilogue: 1/sqrt(64) * log2(e)
#define QSC 0.18033688011112042f

// Scratch (device globals, fp16) — Q, K, V all [B*H][N][64] row-major
__device__ __half g_q[Bv*Hv*Nv*HDv];   // pre-scaled by QSC
__device__ __half g_k[Bv*Hv*Nv*HDv];
__device__ __half g_v[Bv*Hv*Nv*HDv];   // row-major; transposed in-attn via ldmatrix.trans
__device__ __half g_o[Mv*Dv];          // [B][N][D]
__device__ __half g_xc[Mv*Dv];
__device__ __half g_wq[E3v*Dv];
__device__ __half g_wp[Dv*Dv];

// ============================================================================
// Helpers
// ============================================================================
__device__ __forceinline__ uint32_t smem_u32(const void* p) {
    uint32_t a;
    asm("{ .reg .u64 t; cvta.to.shared.u64 t, %1; cvt.u32.u64 %0, t; }"
        : "=r"(a) : "l"(p));
    return a;
}
__device__ __forceinline__ void cp16(uint32_t dst, const void* src) {
    asm volatile("cp.async.cg.shared.global [%0], [%1], 16;" :: "r"(dst), "l"(src));
}
__device__ __forceinline__ void ldm_x4(uint32_t r[4], uint32_t addr) {
    asm volatile("ldmatrix.sync.aligned.m8n8.x4.shared.b16 {%0,%1,%2,%3}, [%4];"
        : "=r"(r[0]), "=r"(r[1]), "=r"(r[2]), "=r"(r[3]) : "r"(addr));
}
__device__ __forceinline__ void ldm_x4_t(uint32_t r[4], uint32_t addr) {
    asm volatile("ldmatrix.sync.aligned.m8n8.x4.trans.shared.b16 {%0,%1,%2,%3}, [%4];"
        : "=r"(r[0]), "=r"(r[1]), "=r"(r[2]), "=r"(r[3]) : "r"(addr));
}
__device__ __forceinline__ void mma_f16(float c[4], const uint32_t a[4],
                                        uint32_t b0, uint32_t b1) {
    asm volatile(
        "mma.sync.aligned.m16n8k16.row.col.f32.f16.f16.f32 "
        "{%0,%1,%2,%3}, {%4,%5,%6,%7}, {%8,%9}, {%0,%1,%2,%3};"
        : "+f"(c[0]), "+f"(c[1]), "+f"(c[2]), "+f"(c[3])
        : "r"(a[0]), "r"(a[1]), "r"(a[2]), "r"(a[3]), "r"(b0), "r"(b1));
}
// MUFU exp2 (2-ulp approx; underflows to 0 for large-negative inputs)
__device__ __forceinline__ float ex2(float d) {
    float r;
    asm("ex2.approx.f32 %0, %1;" : "=f"(r) : "f"(d));
    return r;
}
__device__ __forceinline__ uint32_t h2u(__half2 h) {
    return *reinterpret_cast<uint32_t*>(&h);
}

// ============================================================================
// Merged fp16 conversion prepass (x, Wqkv, Wproj)
// ============================================================================
#define N4X (Mv*Dv/4)
#define N4Q (E3v*Dv/4)
#define N4P (Dv*Dv/4)
#define N4ALL (N4X + N4Q + N4P)

__global__ void cvt_all_k(const float4* __restrict__ x,
                          const float4* __restrict__ wq,
                          const float4* __restrict__ wp)
{
    int i = blockIdx.x * 256 + threadIdx.x;
    if (i >= N4ALL) return;
    float4 v;
    uint2* d;
    if (i < N4X)            { v = x[i];                d = (uint2*)g_xc + i; }
    else if (i < N4X + N4Q) { v = wq[i - N4X];         d = (uint2*)g_wq + (i - N4X); }
    else                    { v = wp[i - N4X - N4Q];   d = (uint2*)g_wp + (i - N4X - N4Q); }
    *d = make_uint2(h2u(__floats2half2_rn(v.x, v.y)),
                    h2u(__floats2half2_rn(v.z, v.w)));
}

// ============================================================================
// fp16 mma.sync GEMM (NT): 128xTN tile, 256 threads / 8 warps,
// TN=128: warps 2x4 (warp 64x32);  TN=64: warps 4x2 (warp 32x32).
// K-chunk 64, 3-stage ring, one barrier per chunk, ldmatrix loads.
// MODE 0: A=g_xc, B=g_wq -> coalesced stores into g_q (xQSC) / g_k / g_v
// MODE 1: A=g_o,  B=g_wp -> out + bias (fp32)
// ============================================================================
#define KCH 64
#define NCH (Dv / KCH)               /* 12 */
#define LDPH 72                      /* pitch in halves (144B rows) */

template<int MODE, int TN>
__global__ __launch_bounds__(256, 2) void gemm_mma(
    const __half* __restrict__ A, const __half* __restrict__ Bw,
    const float* __restrict__ bias, float* __restrict__ out)
{
    constexpr int WMs  = (TN == 128) ? 2 : 4;
    constexpr int WMsz = 128 / WMs;
    constexpr int MF   = WMsz / 16;
    constexpr int ASTG = 128 * LDPH;
    constexpr int BSTG = TN * LDPH;
    constexpr int STGH = ASTG + BSTG;

    extern __shared__ __align__(16) __half shh[];
    const int tid = threadIdx.x;
    const int w = tid >> 5, lane = tid & 31;
    const int lq = lane >> 2, lr4 = lane & 3;
    const int lrow = ((lane >> 3) & 1) * 8 + (lane & 7);
    const int lcol = (lane >> 4) * 8;
    const int wm = (w % WMs) * WMsz;
    const int wn = (w / WMs) * 32;
    const int m0 = blockIdx.y * 128, e0 = blockIdx.x * TN;

    float c[MF][4][4];
    #pragma unroll
    for (int i = 0; i < MF; i++)
        #pragma unroll
        for (int j = 0; j < 4; j++)
            #pragma unroll
            for (int r = 0; r < 4; r++) c[i][j][r] = 0.f;

    auto load_st = [&](int ch, int stg) {
        __half* Ab = shh + stg * STGH;
        __half* Bb = Ab + ASTG;
        const __half* Ag = A + (size_t)m0 * Dv + ch * KCH;
        const __half* Bg = Bw + (size_t)e0 * Dv + ch * KCH;
        #pragma unroll
        for (int u = 0; u < 4; u++) {
            int idx = tid + 256 * u;
            int row = idx >> 3, q = idx & 7;
            cp16(smem_u32(Ab + row * LDPH + q * 8), Ag + (size_t)row * Dv + q * 8);
        }
        #pragma unroll
        for (int u = 0; u < TN / 32; u++) {
            int idx = tid + 256 * u;
            int row = idx >> 3, q = idx & 7;
            cp16(smem_u32(Bb + row * LDPH + q * 8), Bg + (size_t)row * Dv + q * 8);
        }
        asm volatile("cp.async.commit_group;" ::: "memory");
    };

    load_st(0, 0);
    load_st(1, 1);

    for (int ch = 0; ch < NCH; ch++) {
        if (ch < NCH - 1)
            asm volatile("cp.async.wait_group 1;" ::: "memory");
        else
            asm volatile("cp.async.wait_group 0;" ::: "memory");
        __syncthreads();
        if (ch + 2 < NCH) load_st(ch + 2, (ch + 2) % 3);

        const uint32_t ab32 = smem_u32(shh + (ch % 3) * STGH);
        const uint32_t bb32 = ab32 + ASTG * 2;

        #pragma unroll
        for (int kk = 0; kk < 4; kk++) {
            uint32_t af[MF][4];
            #pragma unroll
            for (int mf = 0; mf < MF; mf++)
                ldm_x4(af[mf], ab32 + ((wm + mf * 16 + lrow) * LDPH + kk * 16 + lcol) * 2);
            uint32_t bq[2][4];
            #pragma unroll
            for (int j = 0; j < 2; j++)
                ldm_x4(bq[j], bb32 + ((wn + j * 16 + lrow) * LDPH + kk * 16 + lcol) * 2);
            #pragma unroll
            for (int mf = 0; mf < MF; mf++) {
                mma_f16(c[mf][0], af[mf], bq[0][0], bq[0][2]);
                mma_f16(c[mf][1], af[mf], bq[0][1], bq[0][3]);
                mma_f16(c[mf][2], af[mf], bq[1][0], bq[1][2]);
                mma_f16(c[mf][3], af[mf], bq[1][1], bq[1][3]);
            }
        }
    }

    // Epilogue (MODE 0: all of Q/K/V coalesced row-major uint32 stores)
    #pragma unroll
    for (int nf = 0; nf < 4; nf++) {
        const int e = e0 + wn + nf * 8 + lr4 * 2;
        #pragma unroll
        for (int mf = 0; mf < MF; mf++) {
            #pragma unroll
            for (int half = 0; half < 2; half++) {
                const int m = m0 + wm + mf * 16 + lq + half * 8;
                float2 v = make_float2(c[mf][nf][half * 2], c[mf][nf][half * 2 + 1]);
                if (MODE == 0) {
                    const int b = m >> 10, n = m & 1023;
                    const int s = e / Dv, r = e - s * Dv;
                    const int hh = r >> 6, i2 = r & 63;
                    if (s == 0) { v.x *= QSC; v.y *= QSC; }
                    __half* dst = ((s == 0) ? g_q : (s == 1 ? g_k : g_v))
                                + (((size_t)(b * Hv + hh)) * Nv + n) * HDv + i2;
                    *(uint32_t*)dst = h2u(__floats2half2_rn(v.x, v.y));
                } else {
                    v.x += bias[e];
                    v.y += bias[e + 1];
                    *(float2*)(out + (size_t)m * Dv + e) = v;
                }
            }
        }
    }
}

#define GSMEM0 (3 * (128 + 128) * LDPH * 2)   /* 110592 */
#define GSMEM1 (3 * (128 + 64)  * LDPH * 2)   /* 82944  */

// ============================================================================
// fp16 mma.sync flash attention: 256 threads / 8 warps x m16.
// Interleaved per-key-block pipeline: for each 16-key block j,
// S_j (tensor) -> ex2_j (MUFU) -> pack -> PV_j (tensor); blocks independent,
// so tensor and MUFU overlap instead of phase-alternating.
// No-max softmax, P in registers, row sums via P x ones MMA, 3-stage KV ring,
// V row-major + ldmatrix.trans. CTA = (bh, 128-row q tile).
// ============================================================================
#define ATP 72
#define AT_SMEM ((3*64*ATP*2 + 128*ATP) * 2 + Nv * 4)   /* 77824 */
#define ONES_H2 0x3C003C00u   /* __half2(1,1) */

__global__ __launch_bounds__(256, 2) void attn_mma(const int* __restrict__ maskg)
{
    extern __shared__ __align__(16) __half sha[];

    const int tid = threadIdx.x;
    const int w = tid >> 5, lane = tid & 31;
    const int lq = lane >> 2, lr4 = lane & 3;
    const int lrow = ((lane >> 3) & 1) * 8 + (lane & 7);
    const int lcol = (lane >> 4) * 8;
    const int bh = blockIdx.y, b = bh / Hv, h = bh - b * Hv;
    const int q0 = blockIdx.x * 128;
    const int wm = w * 16;

    __half* Ks[3] = { sha, sha + 64 * ATP, sha + 2 * 64 * ATP };
    __half* Vs[3] = { sha + 3 * 64 * ATP, sha + 4 * 64 * ATP, sha + 5 * 64 * ATP };
    __half* Qs = sha + 6 * 64 * ATP;            // 128 x ATP
    float*  kb = (float*)(Qs + 128 * ATP);      // key bias [1024]

    const __half* qg = g_q + ((size_t)bh * Nv + q0) * HDv;
    const __half* kg = g_k + (size_t)bh * Nv * HDv;
    const __half* vg = g_v + (size_t)bh * Nv * HDv;   // row-major [n][d]

    // Stage Q (128 x 64 halves)
    #pragma unroll
    for (int u = 0; u < 4; u++) {
        int idx = tid + 256 * u;
        int row = idx >> 3, q = idx & 7;
        cp16(smem_u32(Qs + row * ATP + q * 8), qg + (size_t)row * HDv + q * 8);
    }
    asm volatile("cp.async.commit_group;" ::: "memory");

    // Key bias: 0 valid, -1e5 masked (ex2 underflows to exact 0)
    #pragma unroll
    for (int u = 0; u < 4; u++) {
        int i = tid + 256 * u;
        kb[i] = maskg[b * Nv + i] ? 0.f : -1e5f;
    }

    auto load_kv = [&](int kt, int stg) {
        const __half* ktg = kg + (size_t)kt * 64 * HDv;
        const __half* vtg = vg + (size_t)kt * 64 * HDv;
        __half* Kd = Ks[stg];
        __half* Vd = Vs[stg];
        #pragma unroll
        for (int u = 0; u < 2; u++) {
            int idx = tid + 256 * u;
            int row = idx >> 3, q = idx & 7;
            cp16(smem_u32(Kd + row * ATP + q * 8), ktg + (size_t)row * HDv + q * 8);
            cp16(smem_u32(Vd + row * ATP + q * 8), vtg + (size_t)row * HDv + q * 8);
        }
        asm volatile("cp.async.commit_group;" ::: "memory");
    };
    load_kv(0, 0);
    load_kv(1, 1);

    asm volatile("cp.async.wait_group 2;" ::: "memory");
    __syncthreads();   // Q + kb visible

    // Q fragments via ldmatrix (pre-scaled by QSC)
    uint32_t qf[4][4];
    {
        const uint32_t q32 = smem_u32(Qs);
        #pragma unroll
        for (int ks = 0; ks < 4; ks++)
            ldm_x4(qf[ks], q32 + ((wm + lrow) * ATP + ks * 16 + lcol) * 2);
    }

    const int mrow0 = q0 + wm + lq, mrow1 = mrow0 + 8;
    const int qv0 = maskg[b * Nv + mrow0];
    const int qv1 = maskg[b * Nv + mrow1];

    float oc[8][4];
    #pragma unroll
    for (int df = 0; df < 8; df++)
        #pragma unroll
        for (int r = 0; r < 4; r++) oc[df][r] = 0.f;
    float lsacc[4] = {0.f, 0.f, 0.f, 0.f};   // row sums via P x ones MMA

    for (int kt = 0; kt < 16; kt++) {
        if (kt < 15) asm volatile("cp.async.wait_group 1;" ::: "memory");
        else         asm volatile("cp.async.wait_group 0;" ::: "memory");
        __syncthreads();
        if (kt + 2 < 16) load_kv(kt + 2, (kt + 2) % 3);

        const uint32_t kc32 = smem_u32(Ks[kt % 3]);
        const uint32_t vc32 = smem_u32(Vs[kt % 3]);
        const int k0g = kt * 64;

        // Per 16-key block j: S_j -> ex2_j -> pack -> PV_j (blocks independent)
        #pragma unroll
        for (int j = 0; j < 4; j++) {
            float sc0[4], sc1[4];
            {
                float2 kbv0 = *(const float2*)&kb[k0g + (2 * j) * 8 + 2 * lr4];
                float2 kbv1 = *(const float2*)&kb[k0g + (2 * j + 1) * 8 + 2 * lr4];
                sc0[0] = kbv0.x; sc0[1] = kbv0.y; sc0[2] = kbv0.x; sc0[3] = kbv0.y;
                sc1[0] = kbv1.x; sc1[1] = kbv1.y; sc1[2] = kbv1.x; sc1[3] = kbv1.y;
            }
            #pragma unroll
            for (int ks = 0; ks < 4; ks++) {
                uint32_t kq[4];
                ldm_x4(kq, kc32 + ((j * 16 + lrow) * ATP + ks * 16 + lcol) * 2);
                mma_f16(sc0, qf[ks], kq[0], kq[2]);
                mma_f16(sc1, qf[ks], kq[1], kq[3]);
            }

            uint32_t pa[4] = {
                h2u(__floats2half2_rn(ex2(sc0[0]), ex2(sc0[1]))),
                h2u(__floats2half2_rn(ex2(sc0[2]), ex2(sc0[3]))),
                h2u(__floats2half2_rn(ex2(sc1[0]), ex2(sc1[1]))),
                h2u(__floats2half2_rn(ex2(sc1[2]), ex2(sc1[3])))
            };

            #pragma unroll
            for (int dj = 0; dj < 4; dj++) {
                uint32_t vq[4];
                ldm_x4_t(vq, vc32 + ((j * 16 + lrow) * ATP + dj * 16 + lcol) * 2);
                mma_f16(oc[2 * dj],     pa, vq[0], vq[1]);
                mma_f16(oc[2 * dj + 1], pa, vq[2], vq[3]);
            }
            mma_f16(lsacc, pa, ONES_H2, ONES_H2);
        }
    }

    // lsacc: every column holds the row sum -> c0 = row lq, c2 = row lq+8
    const float inv0 = 1.f / lsacc[0], inv1 = 1.f / lsacc[2];

    // Epilogue: valid rows -> oc/l; invalid rows -> V[row]
    __half* orow0 = g_o + ((size_t)b * Nv + mrow0) * Dv + h * 64;
    __half* orow1 = g_o + ((size_t)b * Nv + mrow1) * Dv + h * 64;
    #pragma unroll
    for (int df = 0; df < 8; df++) {
        const int cc = df * 8 + 2 * lr4;
        float2 v0, v1;
        if (qv0) {
            v0 = make_float2(oc[df][0] * inv0, oc[df][1] * inv0);
        } else {
            __half2 hv = *(const __half2*)&vg[(size_t)mrow0 * HDv + cc];
            v0 = make_float2(__half2float(hv.x), __half2float(hv.y));
        }
        if (qv1) {
            v1 = make_float2(oc[df][2] * inv1, oc[df][3] * inv1);
        } else {
            __half2 hv = *(const __half2*)&vg[(size_t)mrow1 * HDv + cc];
            v1 = make_float2(__half2float(hv.x), __half2float(hv.y));
        }
        *(uint32_t*)&orow0[cc] = h2u(__floats2half2_rn(v0.x, v0.y));
        *(uint32_t*)&orow1[cc] = h2u(__floats2half2_rn(v1.x, v1.y));
    }
}

// ---------------------------------------------------------------------------
extern "C" void kernel_launch(void* const* d_in, const int* in_sizes, int n_in,
                              void* d_out, int out_size)
{
    const float* x     = (const float*)d_in[0];
    const int*   mask  = (const int*)d_in[1];
    const float* Wqkv  = (const float*)d_in[2];
    const float* Wproj = (const float*)d_in[3];
    const float* bproj = (const float*)d_in[4];
    float* out = (float*)d_out;
    (void)in_sizes; (void)n_in; (void)out_size;

    __half *p_xc, *p_wq, *p_wp, *p_o;
    cudaGetSymbolAddress((void**)&p_xc, g_xc);
    cudaGetSymbolAddress((void**)&p_wq, g_wq);
    cudaGetSymbolAddress((void**)&p_wp, g_wp);
    cudaGetSymbolAddress((void**)&p_o,  g_o);

    cudaFuncSetAttribute((const void*)gemm_mma<0,128>,
                         cudaFuncAttributeMaxDynamicSharedMemorySize, GSMEM0);
    cudaFuncSetAttribute((const void*)gemm_mma<1,64>,
                         cudaFuncAttributeMaxDynamicSharedMemorySize, GSMEM1);
    cudaFuncSetAttribute((const void*)attn_mma,
                         cudaFuncAttributeMaxDynamicSharedMemorySize, AT_SMEM);

    // Single merged prepass: fp32 -> fp16 (rne)
    cvt_all_k<<<(N4ALL + 255) / 256, 256>>>((const float4*)x, (const float4*)Wqkv,
                                            (const float4*)Wproj);

    // QKV projection
    dim3 g1(E3v / 128, Mv / 128);   // (18, 64)
    gemm_mma<0,128><<<g1, 256, GSMEM0>>>(p_xc, p_wq, nullptr, nullptr);

    // Flash attention (interleaved S/softmax/PV pipeline)
    dim3 g2(Nv / 128, Bv * Hv);     // (8, 96)
    attn_mma<<<g2, 256, AT_SMEM>>>(mask);

    // Output projection
    dim3 g3(Dv / 64, Mv / 128);     // (12, 64)
    gemm_mma<1,64><<<g3, 256, GSMEM1>>>(p_o, p_wp, bproj, out);
}

// round 15
// speedup vs baseline: 1.2937x; 1.2280x over previous
#include <cuda_runtime.h>
#include <cuda_fp16.h>
#include <cstdint>

#define Bv 8
#define Nv 1024
#define Dv 768
#define Hv 12
#define HDv 64
#define Mv (Bv*Nv)      /* 8192 */
#define E3v (3*Dv)      /* 2304 */

// folded into Q at QKV epilogue: 1/sqrt(64) * log2(e)
#define QSC 0.18033688011112042f

// Scratch (device globals, fp16) — Q, K, V all [B*H][N][64] row-major
__device__ __half g_q[Bv*Hv*Nv*HDv];   // pre-scaled by QSC
__device__ __half g_k[Bv*Hv*Nv*HDv];
__device__ __half g_v[Bv*Hv*Nv*HDv];
__device__ __half g_o[Mv*Dv];          // [B][N][D]
__device__ __half g_xc[Mv*Dv];
__device__ __half g_wq[E3v*Dv];
__device__ __half g_wp[Dv*Dv];
__device__ int    g_idx[Bv*Nv];        // compacted valid-token indices (padded)
__device__ int    g_nv[Bv];            // valid count per batch

// ============================================================================
// Helpers
// ============================================================================
__device__ __forceinline__ uint32_t smem_u32(const void* p) {
    uint32_t a;
    asm("{ .reg .u64 t; cvta.to.shared.u64 t, %1; cvt.u32.u64 %0, t; }"
        : "=r"(a) : "l"(p));
    return a;
}
__device__ __forceinline__ void cp16(uint32_t dst, const void* src) {
    asm volatile("cp.async.cg.shared.global [%0], [%1], 16;" :: "r"(dst), "l"(src));
}
__device__ __forceinline__ void ldm_x4(uint32_t r[4], uint32_t addr) {
    asm volatile("ldmatrix.sync.aligned.m8n8.x4.shared.b16 {%0,%1,%2,%3}, [%4];"
        : "=r"(r[0]), "=r"(r[1]), "=r"(r[2]), "=r"(r[3]) : "r"(addr));
}
__device__ __forceinline__ void ldm_x4_t(uint32_t r[4], uint32_t addr) {
    asm volatile("ldmatrix.sync.aligned.m8n8.x4.trans.shared.b16 {%0,%1,%2,%3}, [%4];"
        : "=r"(r[0]), "=r"(r[1]), "=r"(r[2]), "=r"(r[3]) : "r"(addr));
}
__device__ __forceinline__ void mma_f16(float c[4], const uint32_t a[4],
                                        uint32_t b0, uint32_t b1) {
    asm volatile(
        "mma.sync.aligned.m16n8k16.row.col.f32.f16.f16.f32 "
        "{%0,%1,%2,%3}, {%4,%5,%6,%7}, {%8,%9}, {%0,%1,%2,%3};"
        : "+f"(c[0]), "+f"(c[1]), "+f"(c[2]), "+f"(c[3])
        : "r"(a[0]), "r"(a[1]), "r"(a[2]), "r"(a[3]), "r"(b0), "r"(b1));
}
__device__ __forceinline__ float ex2(float d) {
    float r;
    asm("ex2.approx.f32 %0, %1;" : "=f"(r) : "f"(d));
    return r;
}
__device__ __forceinline__ uint32_t h2u(__half2 h) {
    return *reinterpret_cast<uint32_t*>(&h);
}

// ============================================================================
// Merged fp16 conversion prepass (x, Wqkv, Wproj)
// ============================================================================
#define N4X (Mv*Dv/4)
#define N4Q (E3v*Dv/4)
#define N4P (Dv*Dv/4)
#define N4ALL (N4X + N4Q + N4P)

__global__ void cvt_all_k(const float4* __restrict__ x,
                          const float4* __restrict__ wq,
                          const float4* __restrict__ wp)
{
    int i = blockIdx.x * 256 + threadIdx.x;
    if (i >= N4ALL) return;
    float4 v;
    uint2* d;
    if (i < N4X)            { v = x[i];                d = (uint2*)g_xc + i; }
    else if (i < N4X + N4Q) { v = wq[i - N4X];         d = (uint2*)g_wq + (i - N4X); }
    else                    { v = wp[i - N4X - N4Q];   d = (uint2*)g_wp + (i - N4X - N4Q); }
    *d = make_uint2(h2u(__floats2half2_rn(v.x, v.y)),
                    h2u(__floats2half2_rn(v.z, v.w)));
}

// ============================================================================
// Valid-token compaction: one CTA of 1024 threads per batch.
// g_idx[b][0..nv) = sorted valid indices; [nv..1024) padded with a valid idx.
// ============================================================================
__global__ void build_idx(const int* __restrict__ mask)
{
    const int b = blockIdx.x, t = threadIdx.x;
    const int lane = t & 31, wid = t >> 5;
    __shared__ int wcnt[32], woff[32];

    const int m = mask[b * Nv + t];
    const unsigned bal = __ballot_sync(0xffffffffu, m != 0);
    if (lane == 0) wcnt[wid] = __popc(bal);
    __syncthreads();
    if (t == 0) {
        int acc = 0;
        for (int i = 0; i < 32; i++) { woff[i] = acc; acc += wcnt[i]; }
        g_nv[b] = acc;
    }
    __syncthreads();
    if (m) {
        int pos = woff[wid] + __popc(bal & ((1u << lane) - 1u));
        g_idx[b * Nv + pos] = t;
    }
    __syncthreads();
    const int nv = g_nv[b];
    const int fill = (nv > 0) ? g_idx[b * Nv] : 0;
    for (int i = nv + t; i < Nv; i += 1024) g_idx[b * Nv + i] = fill;
}

// ============================================================================
// fp16 mma.sync GEMM (NT): 128xTN tile, 256 threads / 8 warps,
// K-chunk 64, 3-stage ring, ldmatrix loads.
// MODE 0: A=g_xc, B=g_wq -> g_q (xQSC) / g_k / g_v; masked rows of V are also
//         copied into g_o (those queries' attention output == their V row).
// MODE 1: A=g_o,  B=g_wp -> out + bias (fp32)
// ============================================================================
#define KCH 64
#define NCH (Dv / KCH)               /* 12 */
#define LDPH 72                      /* pitch in halves (144B rows) */

template<int MODE, int TN>
__global__ __launch_bounds__(256, 2) void gemm_mma(
    const __half* __restrict__ A, const __half* __restrict__ Bw,
    const float* __restrict__ bias, float* __restrict__ out,
    const int* __restrict__ mask)
{
    constexpr int WMs  = (TN == 128) ? 2 : 4;
    constexpr int WMsz = 128 / WMs;
    constexpr int MF   = WMsz / 16;
    constexpr int ASTG = 128 * LDPH;
    constexpr int BSTG = TN * LDPH;
    constexpr int STGH = ASTG + BSTG;

    extern __shared__ __align__(16) __half shh[];
    const int tid = threadIdx.x;
    const int w = tid >> 5, lane = tid & 31;
    const int lq = lane >> 2, lr4 = lane & 3;
    const int lrow = ((lane >> 3) & 1) * 8 + (lane & 7);
    const int lcol = (lane >> 4) * 8;
    const int wm = (w % WMs) * WMsz;
    const int wn = (w / WMs) * 32;
    const int m0 = blockIdx.y * 128, e0 = blockIdx.x * TN;

    float c[MF][4][4];
    #pragma unroll
    for (int i = 0; i < MF; i++)
        #pragma unroll
        for (int j = 0; j < 4; j++)
            #pragma unroll
            for (int r = 0; r < 4; r++) c[i][j][r] = 0.f;

    auto load_st = [&](int ch, int stg) {
        __half* Ab = shh + stg * STGH;
        __half* Bb = Ab + ASTG;
        const __half* Ag = A + (size_t)m0 * Dv + ch * KCH;
        const __half* Bg = Bw + (size_t)e0 * Dv + ch * KCH;
        #pragma unroll
        for (int u = 0; u < 4; u++) {
            int idx = tid + 256 * u;
            int row = idx >> 3, q = idx & 7;
            cp16(smem_u32(Ab + row * LDPH + q * 8), Ag + (size_t)row * Dv + q * 8);
        }
        #pragma unroll
        for (int u = 0; u < TN / 32; u++) {
            int idx = tid + 256 * u;
            int row = idx >> 3, q = idx & 7;
            cp16(smem_u32(Bb + row * LDPH + q * 8), Bg + (size_t)row * Dv + q * 8);
        }
        asm volatile("cp.async.commit_group;" ::: "memory");
    };

    load_st(0, 0);
    load_st(1, 1);

    for (int ch = 0; ch < NCH; ch++) {
        if (ch < NCH - 1)
            asm volatile("cp.async.wait_group 1;" ::: "memory");
        else
            asm volatile("cp.async.wait_group 0;" ::: "memory");
        __syncthreads();
        if (ch + 2 < NCH) load_st(ch + 2, (ch + 2) % 3);

        const uint32_t ab32 = smem_u32(shh + (ch % 3) * STGH);
        const uint32_t bb32 = ab32 + ASTG * 2;

        #pragma unroll
        for (int kk = 0; kk < 4; kk++) {
            uint32_t af[MF][4];
            #pragma unroll
            for (int mf = 0; mf < MF; mf++)
                ldm_x4(af[mf], ab32 + ((wm + mf * 16 + lrow) * LDPH + kk * 16 + lcol) * 2);
            uint32_t bq[2][4];
            #pragma unroll
            for (int j = 0; j < 2; j++)
                ldm_x4(bq[j], bb32 + ((wn + j * 16 + lrow) * LDPH + kk * 16 + lcol) * 2);
            #pragma unroll
            for (int mf = 0; mf < MF; mf++) {
                mma_f16(c[mf][0], af[mf], bq[0][0], bq[0][2]);
                mma_f16(c[mf][1], af[mf], bq[0][1], bq[0][3]);
                mma_f16(c[mf][2], af[mf], bq[1][0], bq[1][2]);
                mma_f16(c[mf][3], af[mf], bq[1][1], bq[1][3]);
            }
        }
    }

    // Epilogue
    #pragma unroll
    for (int nf = 0; nf < 4; nf++) {
        const int e = e0 + wn + nf * 8 + lr4 * 2;
        #pragma unroll
        for (int mf = 0; mf < MF; mf++) {
            #pragma unroll
            for (int half = 0; half < 2; half++) {
                const int m = m0 + wm + mf * 16 + lq + half * 8;
                float2 v = make_float2(c[mf][nf][half * 2], c[mf][nf][half * 2 + 1]);
                if (MODE == 0) {
                    const int b = m >> 10, n = m & 1023;
                    const int s = e / Dv, r = e - s * Dv;
                    const int hh = r >> 6, i2 = r & 63;
                    if (s == 0) { v.x *= QSC; v.y *= QSC; }
                    const uint32_t pk = h2u(__floats2half2_rn(v.x, v.y));
                    __half* dst = ((s == 0) ? g_q : (s == 1 ? g_k : g_v))
                                + (((size_t)(b * Hv + hh)) * Nv + n) * HDv + i2;
                    *(uint32_t*)dst = pk;
                    if (s == 2 && mask[b * Nv + n] == 0) {
                        // masked query's attention output == its own V row
                        *(uint32_t*)&g_o[((size_t)b * Nv + n) * Dv + hh * HDv + i2] = pk;
                    }
                } else {
                    v.x += bias[e];
                    v.y += bias[e + 1];
                    *(float2*)(out + (size_t)m * Dv + e) = v;
                }
            }
        }
    }
}

#define GSMEM0 (3 * (128 + 128) * LDPH * 2)   /* 110592 */
#define GSMEM1 (3 * (128 + 64)  * LDPH * 2)   /* 82944  */

// ============================================================================
// fp16 mma.sync flash attention on the COMPACTED valid-token domain.
// 256 threads / 8 warps x m16; no-max softmax via MUFU ex2; P in registers;
// row sums via P x ones MMA; 3-stage KV ring; V row-major + ldmatrix.trans.
// Q/K/V rows gathered through g_idx; O scattered back through g_idx.
// Key-padding slots (>= nv) masked by -1e5 accumulator seed.
// ============================================================================
#define ATP 72
#define AT_SMEM ((3*64*ATP*2 + 128*ATP) * 2)   /* 73728 */
#define ONES_H2 0x3C003C00u   /* __half2(1,1) */

__global__ __launch_bounds__(256, 2) void attn_mma()
{
    extern __shared__ __align__(16) __half sha[];

    const int tid = threadIdx.x;
    const int w = tid >> 5, lane = tid & 31;
    const int lq = lane >> 2, lr4 = lane & 3;
    const int lrow = ((lane >> 3) & 1) * 8 + (lane & 7);
    const int lcol = (lane >> 4) * 8;
    const int bh = blockIdx.y, b = bh / Hv, h = bh - b * Hv;
    const int q0 = blockIdx.x * 128;
    const int wm = w * 16;

    const int nv = g_nv[b];
    if (q0 >= nv) return;                 // no valid queries in this tile
    const int nkt = (nv + 63) >> 6;       // key tiles over compacted keys
    const int* idx = g_idx + b * Nv;      // padded to 1024 with valid indices

    __half* Ks[3] = { sha, sha + 64 * ATP, sha + 2 * 64 * ATP };
    __half* Vs[3] = { sha + 3 * 64 * ATP, sha + 4 * 64 * ATP, sha + 5 * 64 * ATP };
    __half* Qs = sha + 6 * 64 * ATP;      // 128 x ATP

    const __half* qg = g_q + (size_t)bh * Nv * HDv;
    const __half* kg = g_k + (size_t)bh * Nv * HDv;
    const __half* vg = g_v + (size_t)bh * Nv * HDv;

    // Stage Q: tile row -> global row idx[q0+row] (gather; rows are 128B)
    #pragma unroll
    for (int u = 0; u < 4; u++) {
        int ii = tid + 256 * u;
        int row = ii >> 3, q = ii & 7;
        int gr = idx[q0 + row];
        cp16(smem_u32(Qs + row * ATP + q * 8), qg + (size_t)gr * HDv + q * 8);
    }
    asm volatile("cp.async.commit_group;" ::: "memory");

    auto load_kv = [&](int kt, int stg) {
        __half* Kd = Ks[stg];
        __half* Vd = Vs[stg];
        #pragma unroll
        for (int u = 0; u < 2; u++) {
            int ii = tid + 256 * u;
            int row = ii >> 3, q = ii & 7;
            int gr = idx[kt * 64 + row];
            cp16(smem_u32(Kd + row * ATP + q * 8), kg + (size_t)gr * HDv + q * 8);
            cp16(smem_u32(Vd + row * ATP + q * 8), vg + (size_t)gr * HDv + q * 8);
        }
        asm volatile("cp.async.commit_group;" ::: "memory");
    };
    load_kv(0, 0);
    if (nkt > 1) load_kv(1, 1);

    if (nkt > 1) asm volatile("cp.async.wait_group 2;" ::: "memory");
    else         asm volatile("cp.async.wait_group 1;" ::: "memory");
    __syncthreads();   // Q visible

    // Q fragments via ldmatrix (pre-scaled by QSC)
    uint32_t qf[4][4];
    {
        const uint32_t q32 = smem_u32(Qs);
        #pragma unroll
        for (int ks = 0; ks < 4; ks++)
            ldm_x4(qf[ks], q32 + ((wm + lrow) * ATP + ks * 16 + lcol) * 2);
    }

    float oc[8][4];
    #pragma unroll
    for (int df = 0; df < 8; df++)
        #pragma unroll
        for (int r = 0; r < 4; r++) oc[df][r] = 0.f;
    float lsacc[4] = {0.f, 0.f, 0.f, 0.f};

    for (int kt = 0; kt < nkt; kt++) {
        if (kt + 1 < nkt) asm volatile("cp.async.wait_group 1;" ::: "memory");
        else              asm volatile("cp.async.wait_group 0;" ::: "memory");
        __syncthreads();
        if (kt + 2 < nkt) load_kv(kt + 2, (kt + 2) % 3);

        const uint32_t kc32 = smem_u32(Ks[kt % 3]);
        const uint32_t vc32 = smem_u32(Vs[kt % 3]);
        const int k0g = kt * 64;
        const bool full = (k0g + 64 <= nv);   // uniform per tile

        #pragma unroll
        for (int j = 0; j < 4; j++) {
            float sc0[4], sc1[4];
            if (full) {
                sc0[0]=sc0[1]=sc0[2]=sc0[3]=0.f;
                sc1[0]=sc1[1]=sc1[2]=sc1[3]=0.f;
            } else {
                const int c0 = k0g + (2 * j) * 8 + 2 * lr4;
                const int c1 = k0g + (2 * j + 1) * 8 + 2 * lr4;
                sc0[0] = sc0[2] = (c0     < nv) ? 0.f : -1e5f;
                sc0[1] = sc0[3] = (c0 + 1 < nv) ? 0.f : -1e5f;
                sc1[0] = sc1[2] = (c1     < nv) ? 0.f : -1e5f;
                sc1[1] = sc1[3] = (c1 + 1 < nv) ? 0.f : -1e5f;
            }
            #pragma unroll
            for (int ks = 0; ks < 4; ks++) {
                uint32_t kq[4];
                ldm_x4(kq, kc32 + ((j * 16 + lrow) * ATP + ks * 16 + lcol) * 2);
                mma_f16(sc0, qf[ks], kq[0], kq[2]);
                mma_f16(sc1, qf[ks], kq[1], kq[3]);
            }

            uint32_t pa[4] = {
                h2u(__floats2half2_rn(ex2(sc0[0]), ex2(sc0[1]))),
                h2u(__floats2half2_rn(ex2(sc0[2]), ex2(sc0[3]))),
                h2u(__floats2half2_rn(ex2(sc1[0]), ex2(sc1[1]))),
                h2u(__floats2half2_rn(ex2(sc1[2]), ex2(sc1[3])))
            };

            #pragma unroll
            for (int dj = 0; dj < 4; dj++) {
                uint32_t vq[4];
                ldm_x4_t(vq, vc32 + ((j * 16 + lrow) * ATP + dj * 16 + lcol) * 2);
                mma_f16(oc[2 * dj],     pa, vq[0], vq[1]);
                mma_f16(oc[2 * dj + 1], pa, vq[2], vq[3]);
            }
            mma_f16(lsacc, pa, ONES_H2, ONES_H2);
        }
    }

    // lsacc: every column holds the row sum -> c0 = row lq, c2 = row lq+8
    const float inv0 = 1.f / lsacc[0], inv1 = 1.f / lsacc[2];

    // Scatter O back through idx (only rows < nv are real)
    const int r0 = q0 + wm + lq, r1 = r0 + 8;
    if (r0 < nv) {
        __half* orow = g_o + ((size_t)b * Nv + idx[r0]) * Dv + h * 64;
        #pragma unroll
        for (int df = 0; df < 8; df++) {
            const int cc = df * 8 + 2 * lr4;
            *(uint32_t*)&orow[cc] =
                h2u(__floats2half2_rn(oc[df][0] * inv0, oc[df][1] * inv0));
        }
    }
    if (r1 < nv) {
        __half* orow = g_o + ((size_t)b * Nv + idx[r1]) * Dv + h * 64;
        #pragma unroll
        for (int df = 0; df < 8; df++) {
            const int cc = df * 8 + 2 * lr4;
            *(uint32_t*)&orow[cc] =
                h2u(__floats2half2_rn(oc[df][2] * inv1, oc[df][3] * inv1));
        }
    }
}

// ---------------------------------------------------------------------------
extern "C" void kernel_launch(void* const* d_in, const int* in_sizes, int n_in,
                              void* d_out, int out_size)
{
    const float* x     = (const float*)d_in[0];
    const int*   mask  = (const int*)d_in[1];
    const float* Wqkv  = (const float*)d_in[2];
    const float* Wproj = (const float*)d_in[3];
    const float* bproj = (const float*)d_in[4];
    float* out = (float*)d_out;
    (void)in_sizes; (void)n_in; (void)out_size;

    __half *p_xc, *p_wq, *p_wp, *p_o;
    cudaGetSymbolAddress((void**)&p_xc, g_xc);
    cudaGetSymbolAddress((void**)&p_wq, g_wq);
    cudaGetSymbolAddress((void**)&p_wp, g_wp);
    cudaGetSymbolAddress((void**)&p_o,  g_o);

    cudaFuncSetAttribute((const void*)gemm_mma<0,128>,
                         cudaFuncAttributeMaxDynamicSharedMemorySize, GSMEM0);
    cudaFuncSetAttribute((const void*)gemm_mma<1,64>,
                         cudaFuncAttributeMaxDynamicSharedMemorySize, GSMEM1);
    cudaFuncSetAttribute((const void*)attn_mma,
                         cudaFuncAttributeMaxDynamicSharedMemorySize, AT_SMEM);

    // Prepass: fp32 -> fp16 (rne) + valid-token compaction
    cvt_all_k<<<(N4ALL + 255) / 256, 256>>>((const float4*)x, (const float4*)Wqkv,
                                            (const float4*)Wproj);
    build_idx<<<Bv, 1024>>>(mask);

    // QKV projection (also fills g_o for masked query rows)
    dim3 g1(E3v / 128, Mv / 128);   // (18, 64)
    gemm_mma<0,128><<<g1, 256, GSMEM0>>>(p_xc, p_wq, nullptr, nullptr, mask);

    // Flash attention on the compacted domain
    dim3 g2(Nv / 128, Bv * Hv);     // (8, 96); dead q-tiles exit early
    attn_mma<<<g2, 256, AT_SMEM>>>();

    // Output projection
    dim3 g3(Dv / 64, Mv / 128);     // (12, 64)
    gemm_mma<1,64><<<g3, 256, GSMEM1>>>(p_o, p_wp, bproj, out, nullptr);
}

// round 16
// speedup vs baseline: 1.3850x; 1.0705x over previous
#include <cuda_runtime.h>
#include <cuda_fp16.h>
#include <cstdint>

#define Bv 8
#define Nv 1024
#define Dv 768
#define Hv 12
#define HDv 64
#define Mv (Bv*Nv)      /* 8192 */
#define E3v (3*Dv)      /* 2304 */

// folded into Q at QK epilogue: 1/sqrt(64) * log2(e)
#define QSC 0.18033688011112042f

// Scratch (device globals, fp16) — Q, K, V all [B*H][N][64] row-major
__device__ __half g_q[Bv*Hv*Nv*HDv];   // pre-scaled by QSC
__device__ __half g_k[Bv*Hv*Nv*HDv];
__device__ __half g_v[Bv*Hv*Nv*HDv];
__device__ __half g_o[Mv*Dv];          // [B][N][D]
__device__ __half g_xc[Mv*Dv];
__device__ __half g_wq[E3v*Dv];
__device__ __half g_wp[Dv*Dv];
__device__ int    g_idx[Bv*Nv];        // compacted valid-token indices (padded)
__device__ int    g_nv[Bv];            // valid count per batch

// ============================================================================
// Helpers
// ============================================================================
__device__ __forceinline__ uint32_t smem_u32(const void* p) {
    uint32_t a;
    asm("{ .reg .u64 t; cvta.to.shared.u64 t, %1; cvt.u32.u64 %0, t; }"
        : "=r"(a) : "l"(p));
    return a;
}
__device__ __forceinline__ void cp16(uint32_t dst, const void* src) {
    asm volatile("cp.async.cg.shared.global [%0], [%1], 16;" :: "r"(dst), "l"(src));
}
__device__ __forceinline__ void ldm_x4(uint32_t r[4], uint32_t addr) {
    asm volatile("ldmatrix.sync.aligned.m8n8.x4.shared.b16 {%0,%1,%2,%3}, [%4];"
        : "=r"(r[0]), "=r"(r[1]), "=r"(r[2]), "=r"(r[3]) : "r"(addr));
}
__device__ __forceinline__ void ldm_x4_t(uint32_t r[4], uint32_t addr) {
    asm volatile("ldmatrix.sync.aligned.m8n8.x4.trans.shared.b16 {%0,%1,%2,%3}, [%4];"
        : "=r"(r[0]), "=r"(r[1]), "=r"(r[2]), "=r"(r[3]) : "r"(addr));
}
__device__ __forceinline__ void mma_f16(float c[4], const uint32_t a[4],
                                        uint32_t b0, uint32_t b1) {
    asm volatile(
        "mma.sync.aligned.m16n8k16.row.col.f32.f16.f16.f32 "
        "{%0,%1,%2,%3}, {%4,%5,%6,%7}, {%8,%9}, {%0,%1,%2,%3};"
        : "+f"(c[0]), "+f"(c[1]), "+f"(c[2]), "+f"(c[3])
        : "r"(a[0]), "r"(a[1]), "r"(a[2]), "r"(a[3]), "r"(b0), "r"(b1));
}
__device__ __forceinline__ float ex2(float d) {
    float r;
    asm("ex2.approx.f32 %0, %1;" : "=f"(r) : "f"(d));
    return r;
}
__device__ __forceinline__ uint32_t h2u(__half2 h) {
    return *reinterpret_cast<uint32_t*>(&h);
}

// ============================================================================
// Merged fp16 conversion prepass (x, Wqkv, Wproj)
// ============================================================================
#define N4X (Mv*Dv/4)
#define N4Q (E3v*Dv/4)
#define N4P (Dv*Dv/4)
#define N4ALL (N4X + N4Q + N4P)

__global__ void cvt_all_k(const float4* __restrict__ x,
                          const float4* __restrict__ wq,
                          const float4* __restrict__ wp)
{
    int i = blockIdx.x * 256 + threadIdx.x;
    if (i >= N4ALL) return;
    float4 v;
    uint2* d;
    if (i < N4X)            { v = x[i];                d = (uint2*)g_xc + i; }
    else if (i < N4X + N4Q) { v = wq[i - N4X];         d = (uint2*)g_wq + (i - N4X); }
    else                    { v = wp[i - N4X - N4Q];   d = (uint2*)g_wp + (i - N4X - N4Q); }
    *d = make_uint2(h2u(__floats2half2_rn(v.x, v.y)),
                    h2u(__floats2half2_rn(v.z, v.w)));
}

// ============================================================================
// Valid-token compaction: one CTA of 1024 threads per batch.
// ============================================================================
__global__ void build_idx(const int* __restrict__ mask)
{
    const int b = blockIdx.x, t = threadIdx.x;
    const int lane = t & 31, wid = t >> 5;
    __shared__ int wcnt[32], woff[32];

    const int m = mask[b * Nv + t];
    const unsigned bal = __ballot_sync(0xffffffffu, m != 0);
    if (lane == 0) wcnt[wid] = __popc(bal);
    __syncthreads();
    if (t == 0) {
        int acc = 0;
        for (int i = 0; i < 32; i++) { woff[i] = acc; acc += wcnt[i]; }
        g_nv[b] = acc;
    }
    __syncthreads();
    if (m) {
        int pos = woff[wid] + __popc(bal & ((1u << lane) - 1u));
        g_idx[b * Nv + pos] = t;
    }
    __syncthreads();
    const int nv = g_nv[b];
    const int fill = (nv > 0) ? g_idx[b * Nv] : 0;
    for (int i = nv + t; i < Nv; i += 1024) g_idx[b * Nv + i] = fill;
}

// ============================================================================
// fp16 mma.sync GEMM (NT): 128xTN tile, 256 threads / 8 warps,
// K-chunk 64, 3-stage ring, ldmatrix loads.
// MODE 0: V-projection (Bw = Wqkv V-rows). All M rows. Stores g_v; masked
//         rows also copied to g_o (their attention output == V row).
// MODE 1: out = g_o @ Wproj^T + bias (fp32 out).
// MODE 2: QK-projection on the COMPACTED domain. blockIdx.y = b*8 + tile;
//         A rows gathered via g_idx; tiles with loc0 >= nv exit. Stores
//         g_q (xQSC) / g_k at token positions (padding rows = benign dups).
// ============================================================================
#define KCH 64
#define NCH (Dv / KCH)               /* 12 */
#define LDPH 72                      /* pitch in halves (144B rows) */

template<int MODE, int TN>
__global__ __launch_bounds__(256, 2) void gemm_mma(
    const __half* __restrict__ A, const __half* __restrict__ Bw,
    const float* __restrict__ bias, float* __restrict__ out,
    const int* __restrict__ mask)
{
    constexpr int WMs  = (TN == 128) ? 2 : 4;
    constexpr int WMsz = 128 / WMs;
    constexpr int MF   = WMsz / 16;
    constexpr int ASTG = 128 * LDPH;
    constexpr int BSTG = TN * LDPH;
    constexpr int STGH = ASTG + BSTG;

    extern __shared__ __align__(16) __half shh[];
    const int tid = threadIdx.x;
    const int w = tid >> 5, lane = tid & 31;
    const int lq = lane >> 2, lr4 = lane & 3;
    const int lrow = ((lane >> 3) & 1) * 8 + (lane & 7);
    const int lcol = (lane >> 4) * 8;
    const int wm = (w % WMs) * WMsz;
    const int wn = (w / WMs) * 32;
    const int e0 = blockIdx.x * TN;

    int m0 = 0, bb = 0;
    const int* idxp = nullptr;
    if (MODE == 2) {
        bb = blockIdx.y >> 3;
        const int loc0 = (blockIdx.y & 7) * 128;
        if (loc0 >= g_nv[bb]) return;
        idxp = g_idx + bb * Nv + loc0;
    } else {
        m0 = blockIdx.y * 128;
    }

    float c[MF][4][4];
    #pragma unroll
    for (int i = 0; i < MF; i++)
        #pragma unroll
        for (int j = 0; j < 4; j++)
            #pragma unroll
            for (int r = 0; r < 4; r++) c[i][j][r] = 0.f;

    auto load_st = [&](int ch, int stg) {
        __half* Ab = shh + stg * STGH;
        __half* Bb = Ab + ASTG;
        const __half* Bg = Bw + (size_t)e0 * Dv + ch * KCH;
        #pragma unroll
        for (int u = 0; u < 4; u++) {
            int ii = tid + 256 * u;
            int row = ii >> 3, q = ii & 7;
            const __half* src;
            if (MODE == 2) {
                int gr = idxp[row];
                src = A + ((size_t)(bb * Nv + gr)) * Dv + ch * KCH + q * 8;
            } else {
                src = A + (size_t)(m0 + row) * Dv + ch * KCH + q * 8;
            }
            cp16(smem_u32(Ab + row * LDPH + q * 8), src);
        }
        #pragma unroll
        for (int u = 0; u < TN / 32; u++) {
            int ii = tid + 256 * u;
            int row = ii >> 3, q = ii & 7;
            cp16(smem_u32(Bb + row * LDPH + q * 8), Bg + (size_t)row * Dv + q * 8);
        }
        asm volatile("cp.async.commit_group;" ::: "memory");
    };

    load_st(0, 0);
    load_st(1, 1);

    for (int ch = 0; ch < NCH; ch++) {
        if (ch < NCH - 1)
            asm volatile("cp.async.wait_group 1;" ::: "memory");
        else
            asm volatile("cp.async.wait_group 0;" ::: "memory");
        __syncthreads();
        if (ch + 2 < NCH) load_st(ch + 2, (ch + 2) % 3);

        const uint32_t ab32 = smem_u32(shh + (ch % 3) * STGH);
        const uint32_t bb32 = ab32 + ASTG * 2;

        #pragma unroll
        for (int kk = 0; kk < 4; kk++) {
            uint32_t af[MF][4];
            #pragma unroll
            for (int mf = 0; mf < MF; mf++)
                ldm_x4(af[mf], ab32 + ((wm + mf * 16 + lrow) * LDPH + kk * 16 + lcol) * 2);
            uint32_t bq[2][4];
            #pragma unroll
            for (int j = 0; j < 2; j++)
                ldm_x4(bq[j], bb32 + ((wn + j * 16 + lrow) * LDPH + kk * 16 + lcol) * 2);
            #pragma unroll
            for (int mf = 0; mf < MF; mf++) {
                mma_f16(c[mf][0], af[mf], bq[0][0], bq[0][2]);
                mma_f16(c[mf][1], af[mf], bq[0][1], bq[0][3]);
                mma_f16(c[mf][2], af[mf], bq[1][0], bq[1][2]);
                mma_f16(c[mf][3], af[mf], bq[1][1], bq[1][3]);
            }
        }
    }

    // Epilogue
    #pragma unroll
    for (int nf = 0; nf < 4; nf++) {
        const int e = e0 + wn + nf * 8 + lr4 * 2;
        #pragma unroll
        for (int mf = 0; mf < MF; mf++) {
            #pragma unroll
            for (int half = 0; half < 2; half++) {
                const int mloc = wm + mf * 16 + lq + half * 8;
                float2 v = make_float2(c[mf][nf][half * 2], c[mf][nf][half * 2 + 1]);
                if (MODE == 0) {
                    // V projection: e in [0,768)
                    const int m = m0 + mloc;
                    const int b = m >> 10, n = m & 1023;
                    const int hh = e >> 6, i2 = e & 63;
                    const uint32_t pk = h2u(__floats2half2_rn(v.x, v.y));
                    *(uint32_t*)&g_v[(((size_t)(b * Hv + hh)) * Nv + n) * HDv + i2] = pk;
                    if (mask[b * Nv + n] == 0)
                        *(uint32_t*)&g_o[((size_t)b * Nv + n) * Dv + hh * HDv + i2] = pk;
                } else if (MODE == 2) {
                    // QK projection, compacted rows: e in [0,1536)
                    const int n = idxp[mloc];
                    const int s = e / Dv, rr = e - s * Dv;
                    const int hh = rr >> 6, i2 = rr & 63;
                    if (s == 0) { v.x *= QSC; v.y *= QSC; }
                    __half* dst = ((s == 0) ? g_q : g_k)
                                + (((size_t)(bb * Hv + hh)) * Nv + n) * HDv + i2;
                    *(uint32_t*)dst = h2u(__floats2half2_rn(v.x, v.y));
                } else {
                    const int m = m0 + mloc;
                    v.x += bias[e];
                    v.y += bias[e + 1];
                    *(float2*)(out + (size_t)m * Dv + e) = v;
                }
            }
        }
    }
}

#define GSMEM0 (3 * (128 + 128) * LDPH * 2)   /* 110592 */
#define GSMEM1 (3 * (128 + 64)  * LDPH * 2)   /* 82944  */

// ============================================================================
// fp16 mma.sync flash attention on the COMPACTED valid-token domain.
// ============================================================================
#define ATP 72
#define AT_SMEM ((3*64*ATP*2 + 128*ATP) * 2)   /* 73728 */
#define ONES_H2 0x3C003C00u   /* __half2(1,1) */

__global__ __launch_bounds__(256, 2) void attn_mma()
{
    extern __shared__ __align__(16) __half sha[];

    const int tid = threadIdx.x;
    const int w = tid >> 5, lane = tid & 31;
    const int lq = lane >> 2, lr4 = lane & 3;
    const int lrow = ((lane >> 3) & 1) * 8 + (lane & 7);
    const int lcol = (lane >> 4) * 8;
    const int bh = blockIdx.y, b = bh / Hv, h = bh - b * Hv;
    const int q0 = blockIdx.x * 128;
    const int wm = w * 16;

    const int nv = g_nv[b];
    if (q0 >= nv) return;
    const int nkt = (nv + 63) >> 6;
    const int* idx = g_idx + b * Nv;

    __half* Ks[3] = { sha, sha + 64 * ATP, sha + 2 * 64 * ATP };
    __half* Vs[3] = { sha + 3 * 64 * ATP, sha + 4 * 64 * ATP, sha + 5 * 64 * ATP };
    __half* Qs = sha + 6 * 64 * ATP;

    const __half* qg = g_q + (size_t)bh * Nv * HDv;
    const __half* kg = g_k + (size_t)bh * Nv * HDv;
    const __half* vg = g_v + (size_t)bh * Nv * HDv;

    #pragma unroll
    for (int u = 0; u < 4; u++) {
        int ii = tid + 256 * u;
        int row = ii >> 3, q = ii & 7;
        int gr = idx[q0 + row];
        cp16(smem_u32(Qs + row * ATP + q * 8), qg + (size_t)gr * HDv + q * 8);
    }
    asm volatile("cp.async.commit_group;" ::: "memory");

    auto load_kv = [&](int kt, int stg) {
        __half* Kd = Ks[stg];
        __half* Vd = Vs[stg];
        #pragma unroll
        for (int u = 0; u < 2; u++) {
            int ii = tid + 256 * u;
            int row = ii >> 3, q = ii & 7;
            int gr = idx[kt * 64 + row];
            cp16(smem_u32(Kd + row * ATP + q * 8), kg + (size_t)gr * HDv + q * 8);
            cp16(smem_u32(Vd + row * ATP + q * 8), vg + (size_t)gr * HDv + q * 8);
        }
        asm volatile("cp.async.commit_group;" ::: "memory");
    };
    load_kv(0, 0);
    if (nkt > 1) load_kv(1, 1);

    if (nkt > 1) asm volatile("cp.async.wait_group 2;" ::: "memory");
    else         asm volatile("cp.async.wait_group 1;" ::: "memory");
    __syncthreads();

    uint32_t qf[4][4];
    {
        const uint32_t q32 = smem_u32(Qs);
        #pragma unroll
        for (int ks = 0; ks < 4; ks++)
            ldm_x4(qf[ks], q32 + ((wm + lrow) * ATP + ks * 16 + lcol) * 2);
    }

    float oc[8][4];
    #pragma unroll
    for (int df = 0; df < 8; df++)
        #pragma unroll
        for (int r = 0; r < 4; r++) oc[df][r] = 0.f;
    float lsacc[4] = {0.f, 0.f, 0.f, 0.f};

    for (int kt = 0; kt < nkt; kt++) {
        if (kt + 1 < nkt) asm volatile("cp.async.wait_group 1;" ::: "memory");
        else              asm volatile("cp.async.wait_group 0;" ::: "memory");
        __syncthreads();
        if (kt + 2 < nkt) load_kv(kt + 2, (kt + 2) % 3);

        const uint32_t kc32 = smem_u32(Ks[kt % 3]);
        const uint32_t vc32 = smem_u32(Vs[kt % 3]);
        const int k0g = kt * 64;
        const bool full = (k0g + 64 <= nv);

        #pragma unroll
        for (int j = 0; j < 4; j++) {
            float sc0[4], sc1[4];
            if (full) {
                sc0[0]=sc0[1]=sc0[2]=sc0[3]=0.f;
                sc1[0]=sc1[1]=sc1[2]=sc1[3]=0.f;
            } else {
                const int c0 = k0g + (2 * j) * 8 + 2 * lr4;
                const int c1 = k0g + (2 * j + 1) * 8 + 2 * lr4;
                sc0[0] = sc0[2] = (c0     < nv) ? 0.f : -1e5f;
                sc0[1] = sc0[3] = (c0 + 1 < nv) ? 0.f : -1e5f;
                sc1[0] = sc1[2] = (c1     < nv) ? 0.f : -1e5f;
                sc1[1] = sc1[3] = (c1 + 1 < nv) ? 0.f : -1e5f;
            }
            #pragma unroll
            for (int ks = 0; ks < 4; ks++) {
                uint32_t kq[4];
                ldm_x4(kq, kc32 + ((j * 16 + lrow) * ATP + ks * 16 + lcol) * 2);
                mma_f16(sc0, qf[ks], kq[0], kq[2]);
                mma_f16(sc1, qf[ks], kq[1], kq[3]);
            }

            uint32_t pa[4] = {
                h2u(__floats2half2_rn(ex2(sc0[0]), ex2(sc0[1]))),
                h2u(__floats2half2_rn(ex2(sc0[2]), ex2(sc0[3]))),
                h2u(__floats2half2_rn(ex2(sc1[0]), ex2(sc1[1]))),
                h2u(__floats2half2_rn(ex2(sc1[2]), ex2(sc1[3])))
            };

            #pragma unroll
            for (int dj = 0; dj < 4; dj++) {
                uint32_t vq[4];
                ldm_x4_t(vq, vc32 + ((j * 16 + lrow) * ATP + dj * 16 + lcol) * 2);
                mma_f16(oc[2 * dj],     pa, vq[0], vq[1]);
                mma_f16(oc[2 * dj + 1], pa, vq[2], vq[3]);
            }
            mma_f16(lsacc, pa, ONES_H2, ONES_H2);
        }
    }

    const float inv0 = 1.f / lsacc[0], inv1 = 1.f / lsacc[2];

    const int r0 = q0 + wm + lq, r1 = r0 + 8;
    if (r0 < nv) {
        __half* orow = g_o + ((size_t)b * Nv + idx[r0]) * Dv + h * 64;
        #pragma unroll
        for (int df = 0; df < 8; df++) {
            const int cc = df * 8 + 2 * lr4;
            *(uint32_t*)&orow[cc] =
                h2u(__floats2half2_rn(oc[df][0] * inv0, oc[df][1] * inv0));
        }
    }
    if (r1 < nv) {
        __half* orow = g_o + ((size_t)b * Nv + idx[r1]) * Dv + h * 64;
        #pragma unroll
        for (int df = 0; df < 8; df++) {
            const int cc = df * 8 + 2 * lr4;
            *(uint32_t*)&orow[cc] =
                h2u(__floats2half2_rn(oc[df][2] * inv1, oc[df][3] * inv1));
        }
    }
}

// ---------------------------------------------------------------------------
extern "C" void kernel_launch(void* const* d_in, const int* in_sizes, int n_in,
                              void* d_out, int out_size)
{
    const float* x     = (const float*)d_in[0];
    const int*   mask  = (const int*)d_in[1];
    const float* Wqkv  = (const float*)d_in[2];
    const float* Wproj = (const float*)d_in[3];
    const float* bproj = (const float*)d_in[4];
    float* out = (float*)d_out;
    (void)in_sizes; (void)n_in; (void)out_size;

    __half *p_xc, *p_wq, *p_wp, *p_o;
    cudaGetSymbolAddress((void**)&p_xc, g_xc);
    cudaGetSymbolAddress((void**)&p_wq, g_wq);
    cudaGetSymbolAddress((void**)&p_wp, g_wp);
    cudaGetSymbolAddress((void**)&p_o,  g_o);

    cudaFuncSetAttribute((const void*)gemm_mma<0,64>,
                         cudaFuncAttributeMaxDynamicSharedMemorySize, GSMEM1);
    cudaFuncSetAttribute((const void*)gemm_mma<2,128>,
                         cudaFuncAttributeMaxDynamicSharedMemorySize, GSMEM0);
    cudaFuncSetAttribute((const void*)gemm_mma<1,64>,
                         cudaFuncAttributeMaxDynamicSharedMemorySize, GSMEM1);
    cudaFuncSetAttribute((const void*)attn_mma,
                         cudaFuncAttributeMaxDynamicSharedMemorySize, AT_SMEM);

    // Prepass: fp32 -> fp16 (rne) + valid-token compaction
    cvt_all_k<<<(N4ALL + 255) / 256, 256>>>((const float4*)x, (const float4*)Wqkv,
                                            (const float4*)Wproj);
    build_idx<<<Bv, 1024>>>(mask);

    // V projection: all tokens (also fills g_o for masked rows)
    dim3 gv(Dv / 64, Mv / 128);           // (12, 64)
    gemm_mma<0,64><<<gv, 256, GSMEM1>>>(p_xc, p_wq + (size_t)2 * Dv * Dv,
                                        nullptr, nullptr, mask);

    // QK projection: compacted rows only (dead tiles exit)
    dim3 gqk((2 * Dv) / 128, Bv * 8);     // (12, 64)
    gemm_mma<2,128><<<gqk, 256, GSMEM0>>>(p_xc, p_wq, nullptr, nullptr, nullptr);

    // Flash attention on the compacted domain
    dim3 g2(Nv / 128, Bv * Hv);           // (8, 96)
    attn_mma<<<g2, 256, AT_SMEM>>>();

    // Output projection
    dim3 g3(Dv / 64, Mv / 128);           // (12, 64)
    gemm_mma<1,64><<<g3, 256, GSMEM1>>>(p_o, p_wp, bproj, out, nullptr);
}

// round 17
// speedup vs baseline: 1.5016x; 1.0842x over previous
#include <cuda_runtime.h>
#include <cuda_fp16.h>
#include <cstdint>

#define Bv 8
#define Nv 1024
#define Dv 768
#define Hv 12
#define HDv 64
#define Mv (Bv*Nv)      /* 8192 */
#define E3v (3*Dv)      /* 2304 */

// folded into Q at QK epilogue: 1/sqrt(64) * log2(e)
#define QSC 0.18033688011112042f

// Scratch (device globals, fp16) — Q, K, V all [B*H][N][64] row-major
__device__ __half g_q[Bv*Hv*Nv*HDv];   // pre-scaled by QSC
__device__ __half g_k[Bv*Hv*Nv*HDv];
__device__ __half g_v[Bv*Hv*Nv*HDv];
__device__ __half g_o[Mv*Dv];          // [B][N][D]
__device__ __half g_xc[Mv*Dv];
__device__ __half g_wq[E3v*Dv];
__device__ __half g_wp[Dv*Dv];
__device__ int    g_idx[Bv*Nv];        // compacted valid-token indices (padded)
__device__ int    g_nv[Bv];            // valid count per batch

// ============================================================================
// Helpers
// ============================================================================
__device__ __forceinline__ uint32_t smem_u32(const void* p) {
    uint32_t a;
    asm("{ .reg .u64 t; cvta.to.shared.u64 t, %1; cvt.u32.u64 %0, t; }"
        : "=r"(a) : "l"(p));
    return a;
}
__device__ __forceinline__ void cp16(uint32_t dst, const void* src) {
    asm volatile("cp.async.cg.shared.global [%0], [%1], 16;" :: "r"(dst), "l"(src));
}
__device__ __forceinline__ void ldm_x4(uint32_t r[4], uint32_t addr) {
    asm volatile("ldmatrix.sync.aligned.m8n8.x4.shared.b16 {%0,%1,%2,%3}, [%4];"
        : "=r"(r[0]), "=r"(r[1]), "=r"(r[2]), "=r"(r[3]) : "r"(addr));
}
__device__ __forceinline__ void ldm_x4_t(uint32_t r[4], uint32_t addr) {
    asm volatile("ldmatrix.sync.aligned.m8n8.x4.trans.shared.b16 {%0,%1,%2,%3}, [%4];"
        : "=r"(r[0]), "=r"(r[1]), "=r"(r[2]), "=r"(r[3]) : "r"(addr));
}
__device__ __forceinline__ void mma_f16(float c[4], const uint32_t a[4],
                                        uint32_t b0, uint32_t b1) {
    asm volatile(
        "mma.sync.aligned.m16n8k16.row.col.f32.f16.f16.f32 "
        "{%0,%1,%2,%3}, {%4,%5,%6,%7}, {%8,%9}, {%0,%1,%2,%3};"
        : "+f"(c[0]), "+f"(c[1]), "+f"(c[2]), "+f"(c[3])
        : "r"(a[0]), "r"(a[1]), "r"(a[2]), "r"(a[3]), "r"(b0), "r"(b1));
}
__device__ __forceinline__ float ex2(float d) {
    float r;
    asm("ex2.approx.f32 %0, %1;" : "=f"(r) : "f"(d));
    return r;
}
__device__ __forceinline__ uint32_t h2u(__half2 h) {
    return *reinterpret_cast<uint32_t*>(&h);
}

// ============================================================================
// Merged fp16 conversion prepass (x, Wqkv, Wproj)
// ============================================================================
#define N4X (Mv*Dv/4)
#define N4Q (E3v*Dv/4)
#define N4P (Dv*Dv/4)
#define N4ALL (N4X + N4Q + N4P)

__global__ void cvt_all_k(const float4* __restrict__ x,
                          const float4* __restrict__ wq,
                          const float4* __restrict__ wp)
{
    int i = blockIdx.x * 256 + threadIdx.x;
    if (i >= N4ALL) return;
    float4 v;
    uint2* d;
    if (i < N4X)            { v = x[i];                d = (uint2*)g_xc + i; }
    else if (i < N4X + N4Q) { v = wq[i - N4X];         d = (uint2*)g_wq + (i - N4X); }
    else                    { v = wp[i - N4X - N4Q];   d = (uint2*)g_wp + (i - N4X - N4Q); }
    *d = make_uint2(h2u(__floats2half2_rn(v.x, v.y)),
                    h2u(__floats2half2_rn(v.z, v.w)));
}

// ============================================================================
// Valid-token compaction: one CTA of 1024 threads per batch.
// ============================================================================
__global__ void build_idx(const int* __restrict__ mask)
{
    const int b = blockIdx.x, t = threadIdx.x;
    const int lane = t & 31, wid = t >> 5;
    __shared__ int wcnt[32], woff[32];

    const int m = mask[b * Nv + t];
    const unsigned bal = __ballot_sync(0xffffffffu, m != 0);
    if (lane == 0) wcnt[wid] = __popc(bal);
    __syncthreads();
    if (t == 0) {
        int acc = 0;
        for (int i = 0; i < 32; i++) { woff[i] = acc; acc += wcnt[i]; }
        g_nv[b] = acc;
    }
    __syncthreads();
    if (m) {
        int pos = woff[wid] + __popc(bal & ((1u << lane) - 1u));
        g_idx[b * Nv + pos] = t;
    }
    __syncthreads();
    const int nv = g_nv[b];
    const int fill = (nv > 0) ? g_idx[b * Nv] : 0;
    for (int i = nv + t; i < Nv; i += 1024) g_idx[b * Nv + i] = fill;
}

#define KCH 64
#define NCH (Dv / KCH)               /* 12 */
#define LDPH 72                      /* pitch in halves (144B rows) */
#define GSMEM0 (3 * (128 + 128) * LDPH * 2)   /* 110592 */
#define GSMEM1 (3 * (128 + 64)  * LDPH * 2)   /* 82944  */

// ============================================================================
// MERGED QKV projection: one grid, 128x128 tiles, 256 thr / 8 warps (2x4).
// blockIdx.x in [0,6):  V columns (e0 = x*128 of 768), ALL rows (m0 = y*128).
//                       Stores g_v; masked rows also copied to g_o.
// blockIdx.x in [6,18): QK columns (e0 = (x-6)*128 of 1536), COMPACTED rows:
//                       y = b*8 + tile; dead tiles exit and backfill.
//                       Stores g_q (xQSC) / g_k (padding rows = benign dups).
// ============================================================================
__global__ __launch_bounds__(256, 2) void gemm_qkv(
    const __half* __restrict__ A, const __half* __restrict__ Wqk,
    const __half* __restrict__ Wv, const int* __restrict__ mask)
{
    constexpr int ASTG = 128 * LDPH;
    constexpr int STGH = 2 * ASTG;

    extern __shared__ __align__(16) __half shh[];
    __shared__ int sidx[128];

    const int tid = threadIdx.x;
    const int w = tid >> 5, lane = tid & 31;
    const int lq = lane >> 2, lr4 = lane & 3;
    const int lrow = ((lane >> 3) & 1) * 8 + (lane & 7);
    const int lcol = (lane >> 4) * 8;
    const int wm = (w & 1) * 64, wn = (w >> 1) * 32;

    const bool isV = blockIdx.x < 6;
    const int e0 = (isV ? blockIdx.x : blockIdx.x - 6) * 128;
    const __half* Bw = isV ? Wv : Wqk;

    int m0 = 0, bb = 0;
    if (isV) {
        m0 = blockIdx.y * 128;
    } else {
        bb = blockIdx.y >> 3;
        const int loc0 = (blockIdx.y & 7) * 128;
        if (loc0 >= g_nv[bb]) return;
        // stage gather indices once
        if (tid < 128) sidx[tid] = g_idx[bb * Nv + loc0 + tid];
        __syncthreads();
    }

    float c[4][4][4];
    #pragma unroll
    for (int i = 0; i < 4; i++)
        #pragma unroll
        for (int j = 0; j < 4; j++)
            #pragma unroll
            for (int r = 0; r < 4; r++) c[i][j][r] = 0.f;

    auto load_st = [&](int ch, int stg) {
        __half* Ab = shh + stg * STGH;
        __half* Bb = Ab + ASTG;
        const __half* Bg = Bw + (size_t)e0 * Dv + ch * KCH;
        #pragma unroll
        for (int u = 0; u < 4; u++) {
            int ii = tid + 256 * u;
            int row = ii >> 3, q = ii & 7;
            const __half* src = isV
                ? A + (size_t)(m0 + row) * Dv + ch * KCH + q * 8
                : A + ((size_t)(bb * Nv + sidx[row])) * Dv + ch * KCH + q * 8;
            cp16(smem_u32(Ab + row * LDPH + q * 8), src);
        }
        #pragma unroll
        for (int u = 0; u < 4; u++) {
            int ii = tid + 256 * u;
            int row = ii >> 3, q = ii & 7;
            cp16(smem_u32(Bb + row * LDPH + q * 8), Bg + (size_t)row * Dv + q * 8);
        }
        asm volatile("cp.async.commit_group;" ::: "memory");
    };

    load_st(0, 0);
    load_st(1, 1);

    for (int ch = 0; ch < NCH; ch++) {
        if (ch < NCH - 1)
            asm volatile("cp.async.wait_group 1;" ::: "memory");
        else
            asm volatile("cp.async.wait_group 0;" ::: "memory");
        __syncthreads();
        if (ch + 2 < NCH) load_st(ch + 2, (ch + 2) % 3);

        const uint32_t ab32 = smem_u32(shh + (ch % 3) * STGH);
        const uint32_t bb32 = ab32 + ASTG * 2;

        #pragma unroll
        for (int kk = 0; kk < 4; kk++) {
            uint32_t af[4][4];
            #pragma unroll
            for (int mf = 0; mf < 4; mf++)
                ldm_x4(af[mf], ab32 + ((wm + mf * 16 + lrow) * LDPH + kk * 16 + lcol) * 2);
            uint32_t bq[2][4];
            #pragma unroll
            for (int j = 0; j < 2; j++)
                ldm_x4(bq[j], bb32 + ((wn + j * 16 + lrow) * LDPH + kk * 16 + lcol) * 2);
            #pragma unroll
            for (int mf = 0; mf < 4; mf++) {
                mma_f16(c[mf][0], af[mf], bq[0][0], bq[0][2]);
                mma_f16(c[mf][1], af[mf], bq[0][1], bq[0][3]);
                mma_f16(c[mf][2], af[mf], bq[1][0], bq[1][2]);
                mma_f16(c[mf][3], af[mf], bq[1][1], bq[1][3]);
            }
        }
    }

    // Epilogue
    #pragma unroll
    for (int nf = 0; nf < 4; nf++) {
        const int e = e0 + wn + nf * 8 + lr4 * 2;
        #pragma unroll
        for (int mf = 0; mf < 4; mf++) {
            #pragma unroll
            for (int half = 0; half < 2; half++) {
                const int mloc = wm + mf * 16 + lq + half * 8;
                float2 v = make_float2(c[mf][nf][half * 2], c[mf][nf][half * 2 + 1]);
                if (isV) {
                    const int m = m0 + mloc;
                    const int b = m >> 10, n = m & 1023;
                    const int hh = e >> 6, i2 = e & 63;
                    const uint32_t pk = h2u(__floats2half2_rn(v.x, v.y));
                    *(uint32_t*)&g_v[(((size_t)(b * Hv + hh)) * Nv + n) * HDv + i2] = pk;
                    if (mask[b * Nv + n] == 0)
                        *(uint32_t*)&g_o[((size_t)b * Nv + n) * Dv + hh * HDv + i2] = pk;
                } else {
                    const int n = sidx[mloc];
                    const int s = e / Dv, rr = e - s * Dv;
                    const int hh = rr >> 6, i2 = rr & 63;
                    if (s == 0) { v.x *= QSC; v.y *= QSC; }
                    __half* dst = ((s == 0) ? g_q : g_k)
                                + (((size_t)(bb * Hv + hh)) * Nv + n) * HDv + i2;
                    *(uint32_t*)dst = h2u(__floats2half2_rn(v.x, v.y));
                }
            }
        }
    }
}

// ============================================================================
// Output projection: out = g_o @ Wproj^T + bias (fp32), 128x64 tiles.
// ============================================================================
__global__ __launch_bounds__(256, 2) void gemm_proj(
    const __half* __restrict__ A, const __half* __restrict__ Bw,
    const float* __restrict__ bias, float* __restrict__ out)
{
    constexpr int ASTG = 128 * LDPH;
    constexpr int BSTG = 64 * LDPH;
    constexpr int STGH = ASTG + BSTG;

    extern __shared__ __align__(16) __half shh[];
    const int tid = threadIdx.x;
    const int w = tid >> 5, lane = tid & 31;
    const int lq = lane >> 2, lr4 = lane & 3;
    const int lrow = ((lane >> 3) & 1) * 8 + (lane & 7);
    const int lcol = (lane >> 4) * 8;
    const int wm = (w & 3) * 32, wn = (w >> 2) * 32;
    const int m0 = blockIdx.y * 128, e0 = blockIdx.x * 64;

    float c[2][4][4];
    #pragma unroll
    for (int i = 0; i < 2; i++)
        #pragma unroll
        for (int j = 0; j < 4; j++)
            #pragma unroll
            for (int r = 0; r < 4; r++) c[i][j][r] = 0.f;

    auto load_st = [&](int ch, int stg) {
        __half* Ab = shh + stg * STGH;
        __half* Bb = Ab + ASTG;
        const __half* Ag = A + (size_t)m0 * Dv + ch * KCH;
        const __half* Bg = Bw + (size_t)e0 * Dv + ch * KCH;
        #pragma unroll
        for (int u = 0; u < 4; u++) {
            int ii = tid + 256 * u;
            int row = ii >> 3, q = ii & 7;
            cp16(smem_u32(Ab + row * LDPH + q * 8), Ag + (size_t)row * Dv + q * 8);
        }
        #pragma unroll
        for (int u = 0; u < 2; u++) {
            int ii = tid + 256 * u;
            int row = ii >> 3, q = ii & 7;
            cp16(smem_u32(Bb + row * LDPH + q * 8), Bg + (size_t)row * Dv + q * 8);
        }
        asm volatile("cp.async.commit_group;" ::: "memory");
    };

    load_st(0, 0);
    load_st(1, 1);

    for (int ch = 0; ch < NCH; ch++) {
        if (ch < NCH - 1)
            asm volatile("cp.async.wait_group 1;" ::: "memory");
        else
            asm volatile("cp.async.wait_group 0;" ::: "memory");
        __syncthreads();
        if (ch + 2 < NCH) load_st(ch + 2, (ch + 2) % 3);

        const uint32_t ab32 = smem_u32(shh + (ch % 3) * STGH);
        const uint32_t bb32 = ab32 + ASTG * 2;

        #pragma unroll
        for (int kk = 0; kk < 4; kk++) {
            uint32_t af[2][4];
            #pragma unroll
            for (int mf = 0; mf < 2; mf++)
                ldm_x4(af[mf], ab32 + ((wm + mf * 16 + lrow) * LDPH + kk * 16 + lcol) * 2);
            uint32_t bq[2][4];
            #pragma unroll
            for (int j = 0; j < 2; j++)
                ldm_x4(bq[j], bb32 + ((wn + j * 16 + lrow) * LDPH + kk * 16 + lcol) * 2);
            #pragma unroll
            for (int mf = 0; mf < 2; mf++) {
                mma_f16(c[mf][0], af[mf], bq[0][0], bq[0][2]);
                mma_f16(c[mf][1], af[mf], bq[0][1], bq[0][3]);
                mma_f16(c[mf][2], af[mf], bq[1][0], bq[1][2]);
                mma_f16(c[mf][3], af[mf], bq[1][1], bq[1][3]);
            }
        }
    }

    #pragma unroll
    for (int nf = 0; nf < 4; nf++) {
        const int e = e0 + wn + nf * 8 + lr4 * 2;
        #pragma unroll
        for (int mf = 0; mf < 2; mf++) {
            #pragma unroll
            for (int half = 0; half < 2; half++) {
                const int m = m0 + wm + mf * 16 + lq + half * 8;
                float2 v = make_float2(c[mf][nf][half * 2], c[mf][nf][half * 2 + 1]);
                v.x += bias[e];
                v.y += bias[e + 1];
                *(float2*)(out + (size_t)m * Dv + e) = v;
            }
        }
    }
}

// ============================================================================
// fp16 mma.sync flash attention on the COMPACTED valid-token domain.
// ============================================================================
#define ATP 72
#define AT_SMEM ((3*64*ATP*2 + 128*ATP) * 2)   /* 73728 */
#define ONES_H2 0x3C003C00u   /* __half2(1,1) */

__global__ __launch_bounds__(256, 2) void attn_mma()
{
    extern __shared__ __align__(16) __half sha[];

    const int tid = threadIdx.x;
    const int w = tid >> 5, lane = tid & 31;
    const int lq = lane >> 2, lr4 = lane & 3;
    const int lrow = ((lane >> 3) & 1) * 8 + (lane & 7);
    const int lcol = (lane >> 4) * 8;
    const int bh = blockIdx.y, b = bh / Hv, h = bh - b * Hv;
    const int q0 = blockIdx.x * 128;
    const int wm = w * 16;

    const int nv = g_nv[b];
    if (q0 >= nv) return;
    const int nkt = (nv + 63) >> 6;
    const int* idx = g_idx + b * Nv;

    __half* Ks[3] = { sha, sha + 64 * ATP, sha + 2 * 64 * ATP };
    __half* Vs[3] = { sha + 3 * 64 * ATP, sha + 4 * 64 * ATP, sha + 5 * 64 * ATP };
    __half* Qs = sha + 6 * 64 * ATP;

    const __half* qg = g_q + (size_t)bh * Nv * HDv;
    const __half* kg = g_k + (size_t)bh * Nv * HDv;
    const __half* vg = g_v + (size_t)bh * Nv * HDv;

    #pragma unroll
    for (int u = 0; u < 4; u++) {
        int ii = tid + 256 * u;
        int row = ii >> 3, q = ii & 7;
        int gr = idx[q0 + row];
        cp16(smem_u32(Qs + row * ATP + q * 8), qg + (size_t)gr * HDv + q * 8);
    }
    asm volatile("cp.async.commit_group;" ::: "memory");

    auto load_kv = [&](int kt, int stg) {
        __half* Kd = Ks[stg];
        __half* Vd = Vs[stg];
        #pragma unroll
        for (int u = 0; u < 2; u++) {
            int ii = tid + 256 * u;
            int row = ii >> 3, q = ii & 7;
            int gr = idx[kt * 64 + row];
            cp16(smem_u32(Kd + row * ATP + q * 8), kg + (size_t)gr * HDv + q * 8);
            cp16(smem_u32(Vd + row * ATP + q * 8), vg + (size_t)gr * HDv + q * 8);
        }
        asm volatile("cp.async.commit_group;" ::: "memory");
    };
    load_kv(0, 0);
    if (nkt > 1) load_kv(1, 1);

    if (nkt > 1) asm volatile("cp.async.wait_group 2;" ::: "memory");
    else         asm volatile("cp.async.wait_group 1;" ::: "memory");
    __syncthreads();

    uint32_t qf[4][4];
    {
        const uint32_t q32 = smem_u32(Qs);
        #pragma unroll
        for (int ks = 0; ks < 4; ks++)
            ldm_x4(qf[ks], q32 + ((wm + lrow) * ATP + ks * 16 + lcol) * 2);
    }

    float oc[8][4];
    #pragma unroll
    for (int df = 0; df < 8; df++)
        #pragma unroll
        for (int r = 0; r < 4; r++) oc[df][r] = 0.f;
    float lsacc[4] = {0.f, 0.f, 0.f, 0.f};

    for (int kt = 0; kt < nkt; kt++) {
        if (kt + 1 < nkt) asm volatile("cp.async.wait_group 1;" ::: "memory");
        else              asm volatile("cp.async.wait_group 0;" ::: "memory");
        __syncthreads();
        if (kt + 2 < nkt) load_kv(kt + 2, (kt + 2) % 3);

        const uint32_t kc32 = smem_u32(Ks[kt % 3]);
        const uint32_t vc32 = smem_u32(Vs[kt % 3]);
        const int k0g = kt * 64;
        const bool full = (k0g + 64 <= nv);

        #pragma unroll
        for (int j = 0; j < 4; j++) {
            float sc0[4], sc1[4];
            if (full) {
                sc0[0]=sc0[1]=sc0[2]=sc0[3]=0.f;
                sc1[0]=sc1[1]=sc1[2]=sc1[3]=0.f;
            } else {
                const int c0 = k0g + (2 * j) * 8 + 2 * lr4;
                const int c1 = k0g + (2 * j + 1) * 8 + 2 * lr4;
                sc0[0] = sc0[2] = (c0     < nv) ? 0.f : -1e5f;
                sc0[1] = sc0[3] = (c0 + 1 < nv) ? 0.f : -1e5f;
                sc1[0] = sc1[2] = (c1     < nv) ? 0.f : -1e5f;
                sc1[1] = sc1[3] = (c1 + 1 < nv) ? 0.f : -1e5f;
            }
            #pragma unroll
            for (int ks = 0; ks < 4; ks++) {
                uint32_t kq[4];
                ldm_x4(kq, kc32 + ((j * 16 + lrow) * ATP + ks * 16 + lcol) * 2);
                mma_f16(sc0, qf[ks], kq[0], kq[2]);
                mma_f16(sc1, qf[ks], kq[1], kq[3]);
            }

            uint32_t pa[4] = {
                h2u(__floats2half2_rn(ex2(sc0[0]), ex2(sc0[1]))),
                h2u(__floats2half2_rn(ex2(sc0[2]), ex2(sc0[3]))),
                h2u(__floats2half2_rn(ex2(sc1[0]), ex2(sc1[1]))),
                h2u(__floats2half2_rn(ex2(sc1[2]), ex2(sc1[3])))
            };

            #pragma unroll
            for (int dj = 0; dj < 4; dj++) {
                uint32_t vq[4];
                ldm_x4_t(vq, vc32 + ((j * 16 + lrow) * ATP + dj * 16 + lcol) * 2);
                mma_f16(oc[2 * dj],     pa, vq[0], vq[1]);
                mma_f16(oc[2 * dj + 1], pa, vq[2], vq[3]);
            }
            mma_f16(lsacc, pa, ONES_H2, ONES_H2);
        }
    }

    const float inv0 = 1.f / lsacc[0], inv1 = 1.f / lsacc[2];

    const int r0 = q0 + wm + lq, r1 = r0 + 8;
    if (r0 < nv) {
        __half* orow = g_o + ((size_t)b * Nv + idx[r0]) * Dv + h * 64;
        #pragma unroll
        for (int df = 0; df < 8; df++) {
            const int cc = df * 8 + 2 * lr4;
            *(uint32_t*)&orow[cc] =
                h2u(__floats2half2_rn(oc[df][0] * inv0, oc[df][1] * inv0));
        }
    }
    if (r1 < nv) {
        __half* orow = g_o + ((size_t)b * Nv + idx[r1]) * Dv + h * 64;
        #pragma unroll
        for (int df = 0; df < 8; df++) {
            const int cc = df * 8 + 2 * lr4;
            *(uint32_t*)&orow[cc] =
                h2u(__floats2half2_rn(oc[df][2] * inv1, oc[df][3] * inv1));
        }
    }
}

// ---------------------------------------------------------------------------
extern "C" void kernel_launch(void* const* d_in, const int* in_sizes, int n_in,
                              void* d_out, int out_size)
{
    const float* x     = (const float*)d_in[0];
    const int*   mask  = (const int*)d_in[1];
    const float* Wqkv  = (const float*)d_in[2];
    const float* Wproj = (const float*)d_in[3];
    const float* bproj = (const float*)d_in[4];
    float* out = (float*)d_out;
    (void)in_sizes; (void)n_in; (void)out_size;

    __half *p_xc, *p_wq, *p_wp, *p_o;
    cudaGetSymbolAddress((void**)&p_xc, g_xc);
    cudaGetSymbolAddress((void**)&p_wq, g_wq);
    cudaGetSymbolAddress((void**)&p_wp, g_wp);
    cudaGetSymbolAddress((void**)&p_o,  g_o);

    cudaFuncSetAttribute((const void*)gemm_qkv,
                         cudaFuncAttributeMaxDynamicSharedMemorySize, GSMEM0);
    cudaFuncSetAttribute((const void*)gemm_proj,
                         cudaFuncAttributeMaxDynamicSharedMemorySize, GSMEM1);
    cudaFuncSetAttribute((const void*)attn_mma,
                         cudaFuncAttributeMaxDynamicSharedMemorySize, AT_SMEM);

    // Prepass: fp32 -> fp16 (rne) + valid-token compaction
    cvt_all_k<<<(N4ALL + 255) / 256, 256>>>((const float4*)x, (const float4*)Wqkv,
                                            (const float4*)Wproj);
    build_idx<<<Bv, 1024>>>(mask);

    // Merged V (all rows) + QK (compacted rows) projection in ONE grid
    dim3 gq(18, 64);
    gemm_qkv<<<gq, 256, GSMEM0>>>(p_xc, p_wq, p_wq + (size_t)2 * Dv * Dv, mask);

    // Flash attention on the compacted domain
    dim3 g2(Nv / 128, Bv * Hv);           // (8, 96)
    attn_mma<<<g2, 256, AT_SMEM>>>();

    // Output projection
    dim3 g3(Dv / 64, Mv / 128);           // (12, 64)
    gemm_proj<<<g3, 256, GSMEM1>>>(p_o, p_wp, bproj, out);
}